// round 1
// baseline (speedup 1.0000x reference)
#include <cuda_runtime.h>
#include <math.h>

// Problem constants
// B=64, LT=1024, LV=576, E=768, K=128
namespace cfg {
constexpr int Bn = 64;
constexpr int LT = 1024;
constexpr int LV = 576;
constexpr int E  = 768;
constexpr int Kd = 128;
}

// ---------------------------------------------------------------------------
// Scratch (device globals — no allocation allowed)
// ---------------------------------------------------------------------------
__device__ float g_wqq [cfg::Bn * cfg::LT * cfg::Kd];   // T @ w_q        [B,LT,K]
__device__ float g_wvv [cfg::Bn * cfg::LV * cfg::Kd];   // I @ w_v        [B,LV,K]
__device__ float g_A1  [cfg::Bn * cfg::E  * cfg::Kd];   // T^T @ wqq      [B,E,K]
__device__ float g_M1  [cfg::Bn * cfg::E  * cfg::Kd];   // w_b^T @ A1     [B,E,K]
__device__ float g_A2  [cfg::Bn * cfg::E  * cfg::Kd];   // I^T @ wvv      [B,E,K]
__device__ float g_H   [cfg::Bn * cfg::E  * cfg::Kd];   // w_b @ A2       [B,E,K]
__device__ float g_wqqc[cfg::Bn * cfg::LV * cfg::Kd];   // I @ M1         [B,LV,K]
__device__ float g_wvvc[cfg::Bn * cfg::LT * cfg::Kd];   // T @ H          [B,LT,K]
__device__ float g_sv  [cfg::Bn * cfg::LV];             // scores / attn v
__device__ float g_sq  [cfg::Bn * cfg::LT];             // scores / attn q
__device__ float g_ctx [cfg::Bn * cfg::E];              // context_v + context_q

// ---------------------------------------------------------------------------
// Register-tiled fp32 GEMM, C[M,128] = op(A) @ B[K,128]
//   TA=false: A is [M,K] row-major
//   TA=true : A is [K,M] row-major (computes A^T @ B)
// BM=64, BN=128, BK=16, 256 threads, per-thread 4x8 tile.
// Requires M % 64 == 0, K % 16 == 0 (true for all shapes here).
// ---------------------------------------------------------------------------
template <bool TA>
__global__ void __launch_bounds__(256) gemm64x128(
    const float* __restrict__ A, const float* __restrict__ Bm,
    float* __restrict__ C, int M, int K,
    long sA, long sB, long sC)
{
    __shared__ __align__(16) float As[16][64];
    __shared__ __align__(16) float Bs[16][128];

    const float* Ab = A  + (long)blockIdx.z * sA;
    const float* Bb = Bm + (long)blockIdx.z * sB;
    float*       Cb = C  + (long)blockIdx.z * sC;

    const int tid = threadIdx.x;
    const int m0  = blockIdx.x * 64;
    const int ty  = tid >> 4;   // 0..15
    const int tx  = tid & 15;   // 0..15

    float acc[4][8];
#pragma unroll
    for (int i = 0; i < 4; i++)
#pragma unroll
        for (int j = 0; j < 8; j++) acc[i][j] = 0.f;

    for (int k0 = 0; k0 < K; k0 += 16) {
        if (TA) {
            // A: [K, M]; tile rows k0..k0+15, cols m0..m0+63 — direct store
            const int r  = tid >> 4;         // 0..15
            const int c4 = (tid & 15) << 2;  // 0..60
            float4 v = *(const float4*)(Ab + (long)(k0 + r) * M + (m0 + c4));
            *(float4*)&As[r][c4] = v;
        } else {
            // A: [M, K]; tile rows m0..m0+63, cols k0..k0+15 — transpose into smem
            const int r  = tid >> 2;         // 0..63
            const int c4 = (tid & 3) << 2;   // 0..12
            float4 v = *(const float4*)(Ab + (long)(m0 + r) * K + (k0 + c4));
            As[c4 + 0][r] = v.x;
            As[c4 + 1][r] = v.y;
            As[c4 + 2][r] = v.z;
            As[c4 + 3][r] = v.w;
        }
        {
            // B tile [16 x 128]: 8 floats per thread
            const int r = tid >> 4;          // 0..15
            const int c = (tid & 15) << 3;   // 0..120
            const float* bp = Bb + (long)(k0 + r) * 128 + c;
            float4 v0 = *(const float4*)(bp);
            float4 v1 = *(const float4*)(bp + 4);
            *(float4*)&Bs[r][c]     = v0;
            *(float4*)&Bs[r][c + 4] = v1;
        }
        __syncthreads();
#pragma unroll
        for (int kk = 0; kk < 16; kk++) {
            float4 a  = *(const float4*)&As[kk][ty << 2];
            float4 b0 = *(const float4*)&Bs[kk][tx << 2];
            float4 b1 = *(const float4*)&Bs[kk][(tx << 2) + 64];
            float av[4] = {a.x, a.y, a.z, a.w};
            float bv[8] = {b0.x, b0.y, b0.z, b0.w, b1.x, b1.y, b1.z, b1.w};
#pragma unroll
            for (int i = 0; i < 4; i++)
#pragma unroll
                for (int j = 0; j < 8; j++)
                    acc[i][j] = fmaf(av[i], bv[j], acc[i][j]);
        }
        __syncthreads();
    }

#pragma unroll
    for (int i = 0; i < 4; i++) {
        long row = m0 + (ty << 2) + i;
        float4 o0 = make_float4(acc[i][0], acc[i][1], acc[i][2], acc[i][3]);
        float4 o1 = make_float4(acc[i][4], acc[i][5], acc[i][6], acc[i][7]);
        *(float4*)(Cb + row * 128 + (tx << 2))      = o0;
        *(float4*)(Cb + row * 128 + (tx << 2) + 64) = o1;
    }
}

// ---------------------------------------------------------------------------
// score[i] = sum_k tanh(U[i,k] + V[i,k]) * wh[k]   (K=128, one warp per row)
// ---------------------------------------------------------------------------
__global__ void score_kernel(const float* __restrict__ U,
                             const float* __restrict__ Vc,
                             const float* __restrict__ wh,
                             float* __restrict__ s, int total)
{
    int gw   = (blockIdx.x * blockDim.x + threadIdx.x) >> 5;
    int lane = threadIdx.x & 31;
    if (gw >= total) return;
    const float* u = U  + (long)gw * 128;
    const float* v = Vc + (long)gw * 128;
    float acc = 0.f;
#pragma unroll
    for (int k = 0; k < 4; k++) {
        int idx = lane + 32 * k;
        acc += tanhf(u[idx] + v[idx]) * wh[idx];
    }
#pragma unroll
    for (int o = 16; o > 0; o >>= 1)
        acc += __shfl_xor_sync(0xffffffffu, acc, o);
    if (lane == 0) s[gw] = acc;
}

// ---------------------------------------------------------------------------
// in-place row softmax: one block per batch row of length L
// ---------------------------------------------------------------------------
__global__ void softmax_kernel(float* __restrict__ s, int L)
{
    float* row = s + (long)blockIdx.x * L;
    __shared__ float red[32];
    __shared__ float bval;
    const int tid  = threadIdx.x;
    const int lane = tid & 31;
    const int wid  = tid >> 5;
    const int nw   = blockDim.x >> 5;

    float m = -1e30f;
    for (int i = tid; i < L; i += blockDim.x) m = fmaxf(m, row[i]);
#pragma unroll
    for (int o = 16; o > 0; o >>= 1) m = fmaxf(m, __shfl_xor_sync(0xffffffffu, m, o));
    if (lane == 0) red[wid] = m;
    __syncthreads();
    if (tid == 0) {
        float mm = red[0];
        for (int w = 1; w < nw; w++) mm = fmaxf(mm, red[w]);
        bval = mm;
    }
    __syncthreads();
    m = bval;
    __syncthreads();

    float sum = 0.f;
    for (int i = tid; i < L; i += blockDim.x) {
        float e = expf(row[i] - m);
        row[i] = e;
        sum += e;
    }
#pragma unroll
    for (int o = 16; o > 0; o >>= 1) sum += __shfl_xor_sync(0xffffffffu, sum, o);
    if (lane == 0) red[wid] = sum;
    __syncthreads();
    if (tid == 0) {
        float ss = 0.f;
        for (int w = 0; w < nw; w++) ss += red[w];
        bval = ss;
    }
    __syncthreads();
    float inv = 1.f / bval;
    for (int i = tid; i < L; i += blockDim.x) row[i] *= inv;
}

// ---------------------------------------------------------------------------
// ctx[b,d] = sum_y av[b,y]*I[b,y,d] + sum_x aq[b,x]*T[b,x,d]
// one block per batch, 768 threads (thread = d)
// ---------------------------------------------------------------------------
__global__ void __launch_bounds__(768) context_kernel(
    const float* __restrict__ T, const float* __restrict__ I,
    const float* __restrict__ aq, const float* __restrict__ av,
    float* __restrict__ ctx)
{
    __shared__ float sq[cfg::LT];
    __shared__ float sv[cfg::LV];
    const int b = blockIdx.x;
    const int d = threadIdx.x;
    for (int i = d; i < cfg::LT; i += 768) sq[i] = aq[(long)b * cfg::LT + i];
    if (d < cfg::LV) sv[d] = av[(long)b * cfg::LV + d];
    __syncthreads();

    const float* Ib = I + (long)b * cfg::LV * cfg::E + d;
    const float* Tb = T + (long)b * cfg::LT * cfg::E + d;
    float acc = 0.f;
#pragma unroll 4
    for (int y = 0; y < cfg::LV; y++) acc += sv[y] * Ib[(long)y * cfg::E];
#pragma unroll 4
    for (int x = 0; x < cfg::LT; x++) acc += sq[x] * Tb[(long)x * cfg::E];
    ctx[(long)b * cfg::E + d] = acc;
}

// ---------------------------------------------------------------------------
// out[b,e] = tanh(sum_d ctx[b,d] * ws[d,e])   (one block per batch)
// ---------------------------------------------------------------------------
__global__ void __launch_bounds__(768) out_kernel(
    const float* __restrict__ ctx, const float* __restrict__ ws,
    float* __restrict__ out)
{
    __shared__ float sc[cfg::E];
    const int b = blockIdx.x;
    const int e = threadIdx.x;
    sc[e] = ctx[(long)b * cfg::E + e];
    __syncthreads();
    float acc = 0.f;
#pragma unroll 8
    for (int d = 0; d < cfg::E; d++)
        acc += sc[d] * ws[(long)d * cfg::E + e];
    out[(long)b * cfg::E + e] = tanhf(acc);
}

// ---------------------------------------------------------------------------
// launch
// ---------------------------------------------------------------------------
extern "C" void kernel_launch(void* const* d_in, const int* in_sizes, int n_in,
                              void* d_out, int out_size)
{
    using namespace cfg;
    const float* T   = (const float*)d_in[0];  // [B, LT, E]
    const float* I   = (const float*)d_in[1];  // [B, LV, E]
    // d_in[2] = text_attention_mask (all-ones, unused by reference)
    const float* wb  = (const float*)d_in[3];  // [E, E]
    const float* wv  = (const float*)d_in[4];  // [E, K]
    const float* wq  = (const float*)d_in[5];  // [E, K]
    const float* whv = (const float*)d_in[6];  // [K, 1]
    const float* whq = (const float*)d_in[7];  // [K, 1]
    const float* ws  = (const float*)d_in[8];  // [E, E]
    float* out = (float*)d_out;                // [B, E]

    float *wqq, *wvv, *A1, *M1, *A2, *H, *wqqc, *wvvc, *sv, *sq, *ctx;
    cudaGetSymbolAddress((void**)&wqq,  g_wqq);
    cudaGetSymbolAddress((void**)&wvv,  g_wvv);
    cudaGetSymbolAddress((void**)&A1,   g_A1);
    cudaGetSymbolAddress((void**)&M1,   g_M1);
    cudaGetSymbolAddress((void**)&A2,   g_A2);
    cudaGetSymbolAddress((void**)&H,    g_H);
    cudaGetSymbolAddress((void**)&wqqc, g_wqqc);
    cudaGetSymbolAddress((void**)&wvvc, g_wvvc);
    cudaGetSymbolAddress((void**)&sv,   g_sv);
    cudaGetSymbolAddress((void**)&sq,   g_sq);
    cudaGetSymbolAddress((void**)&ctx,  g_ctx);

    const dim3 blk(256);

    // 1) wqq = T @ w_q      : [B*LT, E] @ [E, K]
    gemm64x128<false><<<dim3((Bn * LT) / 64, 1, 1), blk>>>(
        T, wq, wqq, Bn * LT, E, 0, 0, 0);

    // 2) wvv = I @ w_v      : [B*LV, E] @ [E, K]
    gemm64x128<false><<<dim3((Bn * LV) / 64, 1, 1), blk>>>(
        I, wv, wvv, Bn * LV, E, 0, 0, 0);

    // 3) A1[b] = T[b]^T @ wqq[b]   : [E, LT] @ [LT, K]
    gemm64x128<true><<<dim3(E / 64, 1, Bn), blk>>>(
        T, wqq, A1, E, LT,
        (long)LT * E, (long)LT * Kd, (long)E * Kd);

    // 4) M1[b] = w_b^T @ A1[b]     : [E, E] @ [E, K]
    gemm64x128<true><<<dim3(E / 64, 1, Bn), blk>>>(
        wb, A1, M1, E, E,
        0, (long)E * Kd, (long)E * Kd);

    // 5) wqqc[b] = I[b] @ M1[b]    : [LV, E] @ [E, K]
    gemm64x128<false><<<dim3(LV / 64, 1, Bn), blk>>>(
        I, M1, wqqc, LV, E,
        (long)LV * E, (long)E * Kd, (long)LV * Kd);

    // 6) A2[b] = I[b]^T @ wvv[b]   : [E, LV] @ [LV, K]
    gemm64x128<true><<<dim3(E / 64, 1, Bn), blk>>>(
        I, wvv, A2, E, LV,
        (long)LV * E, (long)LV * Kd, (long)E * Kd);

    // 7) H[b] = w_b @ A2[b]        : [E, E] @ [E, K]
    gemm64x128<false><<<dim3(E / 64, 1, Bn), blk>>>(
        wb, A2, H, E, E,
        0, (long)E * Kd, (long)E * Kd);

    // 8) wvvc[b] = T[b] @ H[b]     : [LT, E] @ [E, K]
    gemm64x128<false><<<dim3(LT / 64, 1, Bn), blk>>>(
        T, H, wvvc, LT, E,
        (long)LT * E, (long)E * Kd, (long)LT * Kd);

    // scores: s_v = tanh(wvv + wqqc) . w_hv ; s_q = tanh(wqq + wvvc) . w_hq
    {
        int total_v = Bn * LV;
        int total_q = Bn * LT;
        score_kernel<<<(total_v * 32 + 255) / 256, 256>>>(wvv, wqqc, whv, sv, total_v);
        score_kernel<<<(total_q * 32 + 255) / 256, 256>>>(wqq, wvvc, whq, sq, total_q);
    }

    // softmax (in place)
    softmax_kernel<<<Bn, 256>>>(sv, LV);
    softmax_kernel<<<Bn, 256>>>(sq, LT);

    // context + final projection
    context_kernel<<<Bn, 768>>>(T, I, sq, sv, ctx);
    out_kernel<<<Bn, 768>>>(ctx, ws, out);
}

// round 2
// speedup vs baseline: 1.2464x; 1.2464x over previous
#include <cuda_runtime.h>
#include <math.h>

// Problem constants: B=64, LT=1024, LV=576, E=768, K=128
namespace cfg {
constexpr int Bn = 64;
constexpr int LT = 1024;
constexpr int LV = 576;
constexpr int E  = 768;
constexpr int Kd = 128;
}

typedef unsigned long long u64;

// ---------------------------------------------------------------------------
// Packed f32x2 helpers (Blackwell FFMA2 — 2x fp32 FLOP per issue slot)
// ---------------------------------------------------------------------------
__device__ __forceinline__ u64 pk2(float x, float y) {
    u64 r; asm("mov.b64 %0, {%1,%2};" : "=l"(r) : "f"(x), "f"(y)); return r;
}
__device__ __forceinline__ void upk2(u64 v, float& x, float& y) {
    asm("mov.b64 {%0,%1}, %2;" : "=f"(x), "=f"(y) : "l"(v));
}
__device__ __forceinline__ void ffma2(u64& d, u64 a, u64 b) {
    asm("fma.rn.f32x2 %0, %1, %2, %0;" : "+l"(d) : "l"(a), "l"(b));
}

// ---------------------------------------------------------------------------
// Scratch (device globals — no allocation allowed)
// ---------------------------------------------------------------------------
__device__ float g_wqq [cfg::Bn * cfg::LT * cfg::Kd];
__device__ float g_wvv [cfg::Bn * cfg::LV * cfg::Kd];
__device__ float g_A1  [cfg::Bn * cfg::E  * cfg::Kd];
__device__ float g_M1  [cfg::Bn * cfg::E  * cfg::Kd];
__device__ float g_A2  [cfg::Bn * cfg::E  * cfg::Kd];
__device__ float g_H   [cfg::Bn * cfg::E  * cfg::Kd];
__device__ float g_wqqc[cfg::Bn * cfg::LV * cfg::Kd];
__device__ float g_wvvc[cfg::Bn * cfg::LT * cfg::Kd];
__device__ float g_sv  [cfg::Bn * cfg::LV];
__device__ float g_sq  [cfg::Bn * cfg::LT];
__device__ float g_ctx [cfg::Bn * cfg::E];

// ---------------------------------------------------------------------------
// Register-tiled fp32 GEMM with packed FFMA2, C[M,128] = op(A) @ B[K,128]
//   TA=false: A is [M,K] row-major; TA=true: A is [K,M] (computes A^T @ B)
// 256 threads. BM=128 -> 8x8 per-thread tile; BM=64 -> 4x8.
// Requires M % BM == 0, K % 16 == 0.
// ---------------------------------------------------------------------------
template <int BM, bool TA>
__global__ void __launch_bounds__(256) gemmT(
    const float* __restrict__ A, const float* __restrict__ Bm,
    float* __restrict__ C, int M, int K,
    long sA, long sB, long sC)
{
    constexpr int ROWS = BM / 16;     // 8 or 4
    __shared__ __align__(16) float As[16][BM];
    __shared__ __align__(16) float Bs[16][128];

    const float* Ab = A  + (long)blockIdx.z * sA;
    const float* Bb = Bm + (long)blockIdx.z * sB;
    float*       Cb = C  + (long)blockIdx.z * sC;

    const int tid = threadIdx.x;
    const int m0  = blockIdx.x * BM;
    const int ty  = tid >> 4;   // 0..15
    const int tx  = tid & 15;   // 0..15

    u64 acc[ROWS][4];
#pragma unroll
    for (int i = 0; i < ROWS; i++)
#pragma unroll
        for (int p = 0; p < 4; p++) acc[i][p] = 0ull;

    float4 pa0, pa1, pb0, pb1;

    // ---- prefetch loaders (registers only) ----
    auto loadA = [&](int k0) {
        if constexpr (TA) {
            const int r = tid >> 4;
            if constexpr (BM == 128) {
                const int c = (tid & 15) << 3;
                pa0 = *(const float4*)(Ab + (long)(k0 + r) * M + (m0 + c));
                pa1 = *(const float4*)(Ab + (long)(k0 + r) * M + (m0 + c + 4));
            } else {
                const int c = (tid & 15) << 2;
                pa0 = *(const float4*)(Ab + (long)(k0 + r) * M + (m0 + c));
            }
        } else {
            if constexpr (BM == 128) {
                const int r = tid >> 1;
                const int c = (tid & 1) << 3;
                pa0 = *(const float4*)(Ab + (long)(m0 + r) * K + (k0 + c));
                pa1 = *(const float4*)(Ab + (long)(m0 + r) * K + (k0 + c + 4));
            } else {
                const int r = tid >> 2;
                const int c = (tid & 3) << 2;
                pa0 = *(const float4*)(Ab + (long)(m0 + r) * K + (k0 + c));
            }
        }
    };
    auto loadB = [&](int k0) {
        const int r = tid >> 4;
        const int c = (tid & 15) << 3;
        pb0 = *(const float4*)(Bb + (long)(k0 + r) * 128 + c);
        pb1 = *(const float4*)(Bb + (long)(k0 + r) * 128 + c + 4);
    };
    auto storeAB = [&]() {
        if constexpr (TA) {
            const int r = tid >> 4;
            if constexpr (BM == 128) {
                const int c = (tid & 15) << 3;
                *(float4*)&As[r][c]     = pa0;
                *(float4*)&As[r][c + 4] = pa1;
            } else {
                const int c = (tid & 15) << 2;
                *(float4*)&As[r][c] = pa0;
            }
        } else {
            if constexpr (BM == 128) {
                const int r = tid >> 1;
                const int c = (tid & 1) << 3;
                As[c + 0][r] = pa0.x; As[c + 1][r] = pa0.y;
                As[c + 2][r] = pa0.z; As[c + 3][r] = pa0.w;
                As[c + 4][r] = pa1.x; As[c + 5][r] = pa1.y;
                As[c + 6][r] = pa1.z; As[c + 7][r] = pa1.w;
            } else {
                const int r = tid >> 2;
                const int c = (tid & 3) << 2;
                As[c + 0][r] = pa0.x; As[c + 1][r] = pa0.y;
                As[c + 2][r] = pa0.z; As[c + 3][r] = pa0.w;
            }
        }
        const int r = tid >> 4;
        const int c = (tid & 15) << 3;
        *(float4*)&Bs[r][c]     = pb0;
        *(float4*)&Bs[r][c + 4] = pb1;
    };

    loadA(0); loadB(0);

    for (int k0 = 0; k0 < K; k0 += 16) {
        storeAB();
        __syncthreads();
        if (k0 + 16 < K) { loadA(k0 + 16); loadB(k0 + 16); }

#pragma unroll
        for (int kk = 0; kk < 16; kk++) {
            // b pairs read directly as packed 64-bit (conflict-free: 16B stride)
            ulonglong2 b0 = *(const ulonglong2*)&Bs[kk][tx << 2];
            ulonglong2 b1 = *(const ulonglong2*)&Bs[kk][(tx << 2) + 64];
            u64 bp0 = b0.x, bp1 = b0.y, bp2 = b1.x, bp3 = b1.y;

            float av[ROWS];
            {
                float4 a0 = *(const float4*)&As[kk][ty << 2];
                av[0] = a0.x; av[1] = a0.y; av[2] = a0.z; av[3] = a0.w;
            }
            if constexpr (ROWS == 8) {
                float4 a1 = *(const float4*)&As[kk][(ty << 2) + 64];
                av[4] = a1.x; av[5] = a1.y; av[6] = a1.z; av[7] = a1.w;
            }
#pragma unroll
            for (int i = 0; i < ROWS; i++) {
                u64 ad = pk2(av[i], av[i]);
                ffma2(acc[i][0], ad, bp0);
                ffma2(acc[i][1], ad, bp1);
                ffma2(acc[i][2], ad, bp2);
                ffma2(acc[i][3], ad, bp3);
            }
        }
        __syncthreads();
    }

    // epilogue: unpack and store
#pragma unroll
    for (int i = 0; i < ROWS; i++) {
        int rloc = (i < 4) ? ((ty << 2) + i) : (64 + (ty << 2) + (i - 4));
        long row = m0 + rloc;
        float c0, c1, c2, c3, c4, c5, c6, c7;
        upk2(acc[i][0], c0, c1);
        upk2(acc[i][1], c2, c3);
        upk2(acc[i][2], c4, c5);
        upk2(acc[i][3], c6, c7);
        *(float4*)(Cb + row * 128 + (tx << 2))      = make_float4(c0, c1, c2, c3);
        *(float4*)(Cb + row * 128 + (tx << 2) + 64) = make_float4(c4, c5, c6, c7);
    }
}

// ---------------------------------------------------------------------------
// score[i] = sum_k tanh(U[i,k] + V[i,k]) * wh[k]   (K=128, one warp per row)
// ---------------------------------------------------------------------------
__global__ void score_kernel(const float* __restrict__ U,
                             const float* __restrict__ Vc,
                             const float* __restrict__ wh,
                             float* __restrict__ s, int total)
{
    int gw   = (blockIdx.x * blockDim.x + threadIdx.x) >> 5;
    int lane = threadIdx.x & 31;
    if (gw >= total) return;
    const float* u = U  + (long)gw * 128;
    const float* v = Vc + (long)gw * 128;
    float acc = 0.f;
#pragma unroll
    for (int k = 0; k < 4; k++) {
        int idx = lane + 32 * k;
        acc += tanhf(u[idx] + v[idx]) * wh[idx];
    }
#pragma unroll
    for (int o = 16; o > 0; o >>= 1)
        acc += __shfl_xor_sync(0xffffffffu, acc, o);
    if (lane == 0) s[gw] = acc;
}

// ---------------------------------------------------------------------------
// in-place row softmax: one block per batch row of length L
// ---------------------------------------------------------------------------
__global__ void softmax_kernel(float* __restrict__ s, int L)
{
    float* row = s + (long)blockIdx.x * L;
    __shared__ float red[32];
    __shared__ float bval;
    const int tid  = threadIdx.x;
    const int lane = tid & 31;
    const int wid  = tid >> 5;
    const int nw   = blockDim.x >> 5;

    float m = -1e30f;
    for (int i = tid; i < L; i += blockDim.x) m = fmaxf(m, row[i]);
#pragma unroll
    for (int o = 16; o > 0; o >>= 1) m = fmaxf(m, __shfl_xor_sync(0xffffffffu, m, o));
    if (lane == 0) red[wid] = m;
    __syncthreads();
    if (tid == 0) {
        float mm = red[0];
        for (int w = 1; w < nw; w++) mm = fmaxf(mm, red[w]);
        bval = mm;
    }
    __syncthreads();
    m = bval;
    __syncthreads();

    float sum = 0.f;
    for (int i = tid; i < L; i += blockDim.x) {
        float e = expf(row[i] - m);
        row[i] = e;
        sum += e;
    }
#pragma unroll
    for (int o = 16; o > 0; o >>= 1) sum += __shfl_xor_sync(0xffffffffu, sum, o);
    if (lane == 0) red[wid] = sum;
    __syncthreads();
    if (tid == 0) {
        float ss = 0.f;
        for (int w = 0; w < nw; w++) ss += red[w];
        bval = ss;
    }
    __syncthreads();
    float inv = 1.f / bval;
    for (int i = tid; i < L; i += blockDim.x) row[i] *= inv;
}

// ---------------------------------------------------------------------------
// ctx[b,d] = sum_y av[b,y]*I[b,y,d] + sum_x aq[b,x]*T[b,x,d]
// ---------------------------------------------------------------------------
__global__ void __launch_bounds__(768) context_kernel(
    const float* __restrict__ T, const float* __restrict__ I,
    const float* __restrict__ aq, const float* __restrict__ av,
    float* __restrict__ ctx)
{
    __shared__ float sq[cfg::LT];
    __shared__ float sv[cfg::LV];
    const int b = blockIdx.x;
    const int d = threadIdx.x;
    for (int i = d; i < cfg::LT; i += 768) sq[i] = aq[(long)b * cfg::LT + i];
    if (d < cfg::LV) sv[d] = av[(long)b * cfg::LV + d];
    __syncthreads();

    const float* Ib = I + (long)b * cfg::LV * cfg::E + d;
    const float* Tb = T + (long)b * cfg::LT * cfg::E + d;
    float acc = 0.f;
#pragma unroll 4
    for (int y = 0; y < cfg::LV; y++) acc += sv[y] * Ib[(long)y * cfg::E];
#pragma unroll 4
    for (int x = 0; x < cfg::LT; x++) acc += sq[x] * Tb[(long)x * cfg::E];
    ctx[(long)b * cfg::E + d] = acc;
}

// ---------------------------------------------------------------------------
// out[b,e] = tanh(sum_d ctx[b,d] * ws[d,e])   (one block per batch)
// ---------------------------------------------------------------------------
__global__ void __launch_bounds__(768) out_kernel(
    const float* __restrict__ ctx, const float* __restrict__ ws,
    float* __restrict__ out)
{
    __shared__ float sc[cfg::E];
    const int b = blockIdx.x;
    const int e = threadIdx.x;
    sc[e] = ctx[(long)b * cfg::E + e];
    __syncthreads();
    float acc = 0.f;
#pragma unroll 8
    for (int d = 0; d < cfg::E; d++)
        acc += sc[d] * ws[(long)d * cfg::E + e];
    out[(long)b * cfg::E + e] = tanhf(acc);
}

// ---------------------------------------------------------------------------
// launch
// ---------------------------------------------------------------------------
extern "C" void kernel_launch(void* const* d_in, const int* in_sizes, int n_in,
                              void* d_out, int out_size)
{
    using namespace cfg;
    const float* T   = (const float*)d_in[0];  // [B, LT, E]
    const float* I   = (const float*)d_in[1];  // [B, LV, E]
    // d_in[2] = text_attention_mask (all-ones, unused by reference)
    const float* wb  = (const float*)d_in[3];  // [E, E]
    const float* wv  = (const float*)d_in[4];  // [E, K]
    const float* wq  = (const float*)d_in[5];  // [E, K]
    const float* whv = (const float*)d_in[6];  // [K, 1]
    const float* whq = (const float*)d_in[7];  // [K, 1]
    const float* ws  = (const float*)d_in[8];  // [E, E]
    float* out = (float*)d_out;                // [B, E]

    float *wqq, *wvv, *A1, *M1, *A2, *H, *wqqc, *wvvc, *sv, *sq, *ctx;
    cudaGetSymbolAddress((void**)&wqq,  g_wqq);
    cudaGetSymbolAddress((void**)&wvv,  g_wvv);
    cudaGetSymbolAddress((void**)&A1,   g_A1);
    cudaGetSymbolAddress((void**)&M1,   g_M1);
    cudaGetSymbolAddress((void**)&A2,   g_A2);
    cudaGetSymbolAddress((void**)&H,    g_H);
    cudaGetSymbolAddress((void**)&wqqc, g_wqqc);
    cudaGetSymbolAddress((void**)&wvvc, g_wvvc);
    cudaGetSymbolAddress((void**)&sv,   g_sv);
    cudaGetSymbolAddress((void**)&sq,   g_sq);
    cudaGetSymbolAddress((void**)&ctx,  g_ctx);

    const dim3 blk(256);

    // 1) wqq = T @ w_q      : [B*LT, E] @ [E, K]
    gemmT<128, false><<<dim3((Bn * LT) / 128, 1, 1), blk>>>(
        T, wq, wqq, Bn * LT, E, 0, 0, 0);

    // 2) wvv = I @ w_v      : [B*LV, E] @ [E, K]
    gemmT<128, false><<<dim3((Bn * LV) / 128, 1, 1), blk>>>(
        I, wv, wvv, Bn * LV, E, 0, 0, 0);

    // 3) A1[b] = T[b]^T @ wqq[b]   : [E, LT] @ [LT, K]
    gemmT<128, true><<<dim3(E / 128, 1, Bn), blk>>>(
        T, wqq, A1, E, LT,
        (long)LT * E, (long)LT * Kd, (long)E * Kd);

    // 4) M1[b] = w_b^T @ A1[b]     : [E, E] @ [E, K]
    gemmT<128, true><<<dim3(E / 128, 1, Bn), blk>>>(
        wb, A1, M1, E, E,
        0, (long)E * Kd, (long)E * Kd);

    // 5) wqqc[b] = I[b] @ M1[b]    : [LV, E] @ [E, K]   (M=576 -> BM=64)
    gemmT<64, false><<<dim3(LV / 64, 1, Bn), blk>>>(
        I, M1, wqqc, LV, E,
        (long)LV * E, (long)E * Kd, (long)LV * Kd);

    // 6) A2[b] = I[b]^T @ wvv[b]   : [E, LV] @ [LV, K]
    gemmT<128, true><<<dim3(E / 128, 1, Bn), blk>>>(
        I, wvv, A2, E, LV,
        (long)LV * E, (long)LV * Kd, (long)E * Kd);

    // 7) H[b] = w_b @ A2[b]        : [E, E] @ [E, K]
    gemmT<128, false><<<dim3(E / 128, 1, Bn), blk>>>(
        wb, A2, H, E, E,
        0, (long)E * Kd, (long)E * Kd);

    // 8) wvvc[b] = T[b] @ H[b]     : [LT, E] @ [E, K]
    gemmT<128, false><<<dim3(LT / 128, 1, Bn), blk>>>(
        T, H, wvvc, LT, E,
        (long)LT * E, (long)E * Kd, (long)LT * Kd);

    // scores
    {
        int total_v = Bn * LV;
        int total_q = Bn * LT;
        score_kernel<<<(total_v * 32 + 255) / 256, 256>>>(wvv, wqqc, whv, sv, total_v);
        score_kernel<<<(total_q * 32 + 255) / 256, 256>>>(wqq, wvvc, whq, sq, total_q);
    }

    // softmax (in place)
    softmax_kernel<<<Bn, 256>>>(sv, LV);
    softmax_kernel<<<Bn, 256>>>(sq, LT);

    // context + final projection
    context_kernel<<<Bn, 768>>>(T, I, sq, sv, ctx);
    out_kernel<<<Bn, 768>>>(ctx, ws, out);
}

// round 4
// speedup vs baseline: 1.3671x; 1.0968x over previous
#include <cuda_runtime.h>
#include <cuda_bf16.h>
#include <math.h>
#include <stdint.h>

// Problem constants: B=64, LT=1024, LV=576, E=768, K=128
namespace cfg {
constexpr int Bn = 64;
constexpr int LT = 1024;
constexpr int LV = 576;
constexpr int E  = 768;
constexpr int Kd = 128;
}
using bf16 = __nv_bfloat16;

// fp32 -> bf16 hi/lo split
__device__ __forceinline__ void split2(float v, bf16& h, bf16& l) {
    h = __float2bfloat16(v);
    l = __float2bfloat16(v - __bfloat162float(h));
}

// mma.sync m16n8k16 bf16 (baseline PTX ISA, sm_80+ — no 'a' feature needed)
__device__ __forceinline__ void mma16816(float* d, const uint32_t* a, const uint32_t* b) {
    asm volatile(
        "mma.sync.aligned.m16n8k16.row.col.f32.bf16.bf16.f32 "
        "{%0,%1,%2,%3}, {%4,%5,%6,%7}, {%8,%9}, {%0,%1,%2,%3};"
        : "+f"(d[0]), "+f"(d[1]), "+f"(d[2]), "+f"(d[3])
        : "r"(a[0]), "r"(a[1]), "r"(a[2]), "r"(a[3]), "r"(b[0]), "r"(b[1]));
}

// ===========================================================================
// Scratch (device globals; zero-initialized at load)
// ===========================================================================
#define DEV_BF16(name, n) __device__ __align__(256) bf16 name[n]
DEV_BF16(g_Thi,  64 * 1024 * 768);
DEV_BF16(g_Tlo,  64 * 1024 * 768);
DEV_BF16(g_TThi, 64 * 768 * 1024);
DEV_BF16(g_TTlo, 64 * 768 * 1024);
DEV_BF16(g_Ihi,  64 * 576 * 768 + 64 * 768);   // +pad: call5 reads 64 extra rows
DEV_BF16(g_Ilo,  64 * 576 * 768 + 64 * 768);
DEV_BF16(g_IThi, 64 * 768 * 576);
DEV_BF16(g_ITlo, 64 * 768 * 576);
DEV_BF16(g_wbhi,  768 * 768);
DEV_BF16(g_wblo,  768 * 768);
DEV_BF16(g_wbThi, 768 * 768);
DEV_BF16(g_wbTlo, 768 * 768);
DEV_BF16(g_wqThi, 128 * 768);
DEV_BF16(g_wqTlo, 128 * 768);
DEV_BF16(g_wvThi, 128 * 768);
DEV_BF16(g_wvTlo, 128 * 768);
DEV_BF16(g_wqqThi, 64 * 128 * 1024);
DEV_BF16(g_wqqTlo, 64 * 128 * 1024);
DEV_BF16(g_wvvThi, 64 * 128 * 576);
DEV_BF16(g_wvvTlo, 64 * 128 * 576);
DEV_BF16(g_A1Thi, 64 * 128 * 768);
DEV_BF16(g_A1Tlo, 64 * 128 * 768);
DEV_BF16(g_M1Thi, 64 * 128 * 768);
DEV_BF16(g_M1Tlo, 64 * 128 * 768);
DEV_BF16(g_A2Thi, 64 * 128 * 768);
DEV_BF16(g_A2Tlo, 64 * 128 * 768);
DEV_BF16(g_HThi,  64 * 128 * 768);
DEV_BF16(g_HTlo,  64 * 128 * 768);

__device__ float g_wqq [cfg::Bn * cfg::LT * cfg::Kd];
__device__ float g_wvv [cfg::Bn * cfg::LV * cfg::Kd];
__device__ float g_wqqc[cfg::Bn * cfg::LV * cfg::Kd];
__device__ float g_wvvc[cfg::Bn * cfg::LT * cfg::Kd];
__device__ float g_sv  [cfg::Bn * cfg::LV];
__device__ float g_sq  [cfg::Bn * cfg::LT];
__device__ float g_ctx [cfg::Bn * cfg::E];

// ===========================================================================
// Conversion: fp32 [z][R,C] -> bf16 hi/lo [z][R,C] and/or transposed [z][C,R]
// grid (C/32, R/32, z), block (32, 8)
// ===========================================================================
__global__ void conv_split(const float* __restrict__ X, long sX,
                           bf16* hi, bf16* lo, long sHL,
                           bf16* hiT, bf16* loT, long sT,
                           int R, int C)
{
    __shared__ float tile[32][33];
    const float* Xb = X + (long)blockIdx.z * sX;
    const int c0 = blockIdx.x * 32, r0 = blockIdx.y * 32;
    const int tx = threadIdx.x, ty = threadIdx.y;
#pragma unroll
    for (int j = 0; j < 4; j++) {
        int r = r0 + ty + j * 8;
        float v = Xb[(long)r * C + c0 + tx];
        tile[ty + j * 8][tx] = v;
        if (hi) {
            bf16 h, l; split2(v, h, l);
            long o = (long)blockIdx.z * sHL + (long)r * C + c0 + tx;
            hi[o] = h; lo[o] = l;
        }
    }
    __syncthreads();
    if (hiT) {
#pragma unroll
        for (int j = 0; j < 4; j++) {
            int cc = c0 + ty + j * 8;
            int rr = r0 + tx;
            float v = tile[tx][ty + j * 8];
            bf16 h, l; split2(v, h, l);
            long o = (long)blockIdx.z * sT + (long)cc * R + rr;
            hiT[o] = h; loT[o] = l;
        }
    }
}

// ===========================================================================
// HMMA batched GEMM: C[M,128] = A[M,K] @ B[K,128]  (fp32 via bf16x3 split)
//   A: hi/lo bf16 [.., M, K] row-major (+ z*sA)
//   B: hi/lo bf16 [.., 128, K] row-major (B^T, N-major) (+ z*sB)
// Outputs:
//   OUTF: fp32 C [.., M, 128] (+ z*sC), rows m < Mvalid
//   OUTT: bf16 hi/lo C^T laid out [.., (m/RB), 128, RB] (+ z*sCT)
// CTA: 128x128 tile, 256 threads (8 warps 2x4 -> 64x32 warp tiles).
// K % 32 == 0. Double-buffered smem, rows padded to 40 bf16 (conflict-free).
// ===========================================================================
constexpr int PAD = 40;                         // bf16 per smem row
constexpr int MAT = 128 * PAD;                  // 5120 bf16 per matrix tile
constexpr int STAGE = 4 * MAT;                  // Ah, Al, Bh, Bl
static constexpr int SMEM_MMA_BYTES = 2 * STAGE * 2;   // 81920 B

template <bool OUTF, bool OUTT>
__global__ void __launch_bounds__(256) mma_gemm(
    const bf16* __restrict__ Ahi, const bf16* __restrict__ Alo, long sA,
    const bf16* __restrict__ Bhi, const bf16* __restrict__ Blo, long sB,
    float* __restrict__ Cf, long sC,
    bf16* __restrict__ CThi, bf16* __restrict__ CTlo, long sCT,
    int Ktot, int Mvalid, int RB)
{
    extern __shared__ bf16 sm[];

    const int tid  = threadIdx.x;
    const int lane = tid & 31;
    const int wid  = tid >> 5;
    const int wm   = wid & 1;    // 0..1
    const int wn   = wid >> 1;   // 0..3
    const int g    = lane >> 2;  // 0..7
    const int t    = lane & 3;   // 0..3

    const long z  = blockIdx.z;
    const int  m0 = blockIdx.x * 128;

    const bf16* Ah = Ahi + z * sA + (long)m0 * Ktot;
    const bf16* Al = Alo + z * sA + (long)m0 * Ktot;
    const bf16* Bh = Bhi + z * sB;
    const bf16* Bl = Blo + z * sB;

    float acc[4][4][4];
#pragma unroll
    for (int i = 0; i < 4; i++)
#pragma unroll
        for (int j = 0; j < 4; j++)
#pragma unroll
            for (int q = 0; q < 4; q++) acc[i][j][q] = 0.f;

    const int nch = Ktot >> 5;   // K chunks of 32

    auto load_chunk = [&](int c, int stage) {
        const int k0 = c << 5;
        const bf16* srcs[4] = {Ah, Al, Bh, Bl};
        bf16* sb = sm + stage * STAGE;
#pragma unroll
        for (int mt = 0; mt < 4; mt++) {
            const bf16* src = srcs[mt];
            bf16* dst = sb + mt * MAT;
#pragma unroll
            for (int j = 0; j < 2; j++) {
                int idx = tid * 2 + j;        // 0..511
                int row = idx >> 2;           // 0..127
                int c16 = idx & 3;            // 8-bf16 unit
                float4 v = *(const float4*)(src + (long)row * Ktot + k0 + c16 * 8);
                *(float4*)(dst + row * PAD + c16 * 8) = v;
            }
        }
    };

    auto compute_chunk = [&](int stage) {
        const bf16* sb  = sm + stage * STAGE;
        const bf16* pAh = sb + (wm * 64) * PAD;
        const bf16* pAl = pAh + MAT;
        const bf16* pBh = sb + 2 * MAT + (wn * 32) * PAD;
        const bf16* pBl = pBh + MAT;
#pragma unroll
        for (int ks = 0; ks < 2; ks++) {
            const int kc = ks * 16 + 2 * t;
            uint32_t bh[4][2], bl[4][2];
#pragma unroll
            for (int nf = 0; nf < 4; nf++) {
                const bf16* rh = pBh + (nf * 8 + g) * PAD + kc;
                bh[nf][0] = *(const uint32_t*)rh;
                bh[nf][1] = *(const uint32_t*)(rh + 8);
                const bf16* rl = pBl + (nf * 8 + g) * PAD + kc;
                bl[nf][0] = *(const uint32_t*)rl;
                bl[nf][1] = *(const uint32_t*)(rl + 8);
            }
#pragma unroll
            for (int mf = 0; mf < 4; mf++) {
                uint32_t ah[4], al[4];
                const bf16* rh = pAh + (mf * 16 + g) * PAD + kc;
                ah[0] = *(const uint32_t*)rh;
                ah[1] = *(const uint32_t*)(rh + 8 * PAD);
                ah[2] = *(const uint32_t*)(rh + 8);
                ah[3] = *(const uint32_t*)(rh + 8 * PAD + 8);
                const bf16* rl = pAl + (mf * 16 + g) * PAD + kc;
                al[0] = *(const uint32_t*)rl;
                al[1] = *(const uint32_t*)(rl + 8 * PAD);
                al[2] = *(const uint32_t*)(rl + 8);
                al[3] = *(const uint32_t*)(rl + 8 * PAD + 8);
#pragma unroll
                for (int nf = 0; nf < 4; nf++) {
                    mma16816(acc[mf][nf], ah, bh[nf]);   // hi*hi
                    mma16816(acc[mf][nf], ah, bl[nf]);   // hi*lo
                    mma16816(acc[mf][nf], al, bh[nf]);   // lo*hi
                }
            }
        }
    };

    load_chunk(0, 0);
    __syncthreads();
    for (int c = 0; c < nch; c++) {
        if (c + 1 < nch) load_chunk(c + 1, (c + 1) & 1);
        compute_chunk(c & 1);
        __syncthreads();
    }

    // epilogue
#pragma unroll
    for (int mf = 0; mf < 4; mf++) {
#pragma unroll
        for (int nf = 0; nf < 4; nf++) {
            const int mr0 = m0 + wm * 64 + mf * 16 + g;
            const int mr1 = mr0 + 8;
            const int n0  = wn * 32 + nf * 8 + 2 * t;
            const float* cc = acc[mf][nf];
            if (OUTF) {
                if (mr0 < Mvalid)
                    *(float2*)(Cf + z * sC + (long)mr0 * 128 + n0) =
                        make_float2(cc[0], cc[1]);
                if (mr1 < Mvalid)
                    *(float2*)(Cf + z * sC + (long)mr1 * 128 + n0) =
                        make_float2(cc[2], cc[3]);
            }
            if (OUTT) {
#pragma unroll
                for (int q = 0; q < 4; q++) {
                    const int m = (q < 2) ? mr0 : mr1;
                    const int n = n0 + (q & 1);
                    if (m < Mvalid) {
                        const long bb = m / RB, ml = m % RB;
                        bf16 h, l; split2(cc[q], h, l);
                        const long o = z * sCT + bb * (128L * RB) + (long)n * RB + ml;
                        CThi[o] = h;
                        CTlo[o] = l;
                    }
                }
            }
        }
    }
}

// ===========================================================================
// Elementwise tail
// ===========================================================================
__global__ void score_kernel(const float* __restrict__ U,
                             const float* __restrict__ Vc,
                             const float* __restrict__ wh,
                             float* __restrict__ s, int total)
{
    int gw   = (blockIdx.x * blockDim.x + threadIdx.x) >> 5;
    int lane = threadIdx.x & 31;
    if (gw >= total) return;
    const float* u = U  + (long)gw * 128;
    const float* v = Vc + (long)gw * 128;
    float acc = 0.f;
#pragma unroll
    for (int k = 0; k < 4; k++) {
        int idx = lane + 32 * k;
        acc += tanhf(u[idx] + v[idx]) * wh[idx];
    }
#pragma unroll
    for (int o = 16; o > 0; o >>= 1)
        acc += __shfl_xor_sync(0xffffffffu, acc, o);
    if (lane == 0) s[gw] = acc;
}

__global__ void softmax_kernel(float* __restrict__ s, int L)
{
    float* row = s + (long)blockIdx.x * L;
    __shared__ float red[32];
    __shared__ float bval;
    const int tid  = threadIdx.x;
    const int lane = tid & 31;
    const int wid  = tid >> 5;
    const int nw   = blockDim.x >> 5;

    float m = -1e30f;
    for (int i = tid; i < L; i += blockDim.x) m = fmaxf(m, row[i]);
#pragma unroll
    for (int o = 16; o > 0; o >>= 1) m = fmaxf(m, __shfl_xor_sync(0xffffffffu, m, o));
    if (lane == 0) red[wid] = m;
    __syncthreads();
    if (tid == 0) {
        float mm = red[0];
        for (int w = 1; w < nw; w++) mm = fmaxf(mm, red[w]);
        bval = mm;
    }
    __syncthreads();
    m = bval;
    __syncthreads();

    float sum = 0.f;
    for (int i = tid; i < L; i += blockDim.x) {
        float e = expf(row[i] - m);
        row[i] = e;
        sum += e;
    }
#pragma unroll
    for (int o = 16; o > 0; o >>= 1) sum += __shfl_xor_sync(0xffffffffu, sum, o);
    if (lane == 0) red[wid] = sum;
    __syncthreads();
    if (tid == 0) {
        float ss = 0.f;
        for (int w = 0; w < nw; w++) ss += red[w];
        bval = ss;
    }
    __syncthreads();
    float inv = 1.f / bval;
    for (int i = tid; i < L; i += blockDim.x) row[i] *= inv;
}

__global__ void __launch_bounds__(768) context_kernel(
    const float* __restrict__ T, const float* __restrict__ I,
    const float* __restrict__ aq, const float* __restrict__ av,
    float* __restrict__ ctx)
{
    __shared__ float sq[cfg::LT];
    __shared__ float sv[cfg::LV];
    const int b = blockIdx.x;
    const int d = threadIdx.x;
    for (int i = d; i < cfg::LT; i += 768) sq[i] = aq[(long)b * cfg::LT + i];
    if (d < cfg::LV) sv[d] = av[(long)b * cfg::LV + d];
    __syncthreads();

    const float* Ib = I + (long)b * cfg::LV * cfg::E + d;
    const float* Tb = T + (long)b * cfg::LT * cfg::E + d;
    float acc = 0.f;
#pragma unroll 4
    for (int y = 0; y < cfg::LV; y++) acc += sv[y] * Ib[(long)y * cfg::E];
#pragma unroll 4
    for (int x = 0; x < cfg::LT; x++) acc += sq[x] * Tb[(long)x * cfg::E];
    ctx[(long)b * cfg::E + d] = acc;
}

__global__ void __launch_bounds__(768) out_kernel(
    const float* __restrict__ ctx, const float* __restrict__ ws,
    float* __restrict__ out)
{
    __shared__ float sc[cfg::E];
    const int b = blockIdx.x;
    const int e = threadIdx.x;
    sc[e] = ctx[(long)b * cfg::E + e];
    __syncthreads();
    float acc = 0.f;
#pragma unroll 8
    for (int d = 0; d < cfg::E; d++)
        acc += sc[d] * ws[(long)d * cfg::E + e];
    out[(long)b * cfg::E + e] = tanhf(acc);
}

// ===========================================================================
// launch
// ===========================================================================
extern "C" void kernel_launch(void* const* d_in, const int* in_sizes, int n_in,
                              void* d_out, int out_size)
{
    using namespace cfg;
    const float* T   = (const float*)d_in[0];
    const float* I   = (const float*)d_in[1];
    const float* wb  = (const float*)d_in[3];
    const float* wv  = (const float*)d_in[4];
    const float* wq  = (const float*)d_in[5];
    const float* whv = (const float*)d_in[6];
    const float* whq = (const float*)d_in[7];
    const float* ws  = (const float*)d_in[8];
    float* out = (float*)d_out;

    bf16 *Thi, *Tlo, *TThi, *TTlo, *Ihi, *Ilo, *IThi, *ITlo;
    bf16 *wbhi, *wblo, *wbThi, *wbTlo, *wqThi, *wqTlo, *wvThi, *wvTlo;
    bf16 *wqqThi, *wqqTlo, *wvvThi, *wvvTlo;
    bf16 *A1Thi, *A1Tlo, *M1Thi, *M1Tlo, *A2Thi, *A2Tlo, *HThi, *HTlo;
    float *wqq, *wvv, *wqqc, *wvvc, *sv, *sq, *ctx;

    cudaGetSymbolAddress((void**)&Thi, g_Thi);   cudaGetSymbolAddress((void**)&Tlo, g_Tlo);
    cudaGetSymbolAddress((void**)&TThi, g_TThi); cudaGetSymbolAddress((void**)&TTlo, g_TTlo);
    cudaGetSymbolAddress((void**)&Ihi, g_Ihi);   cudaGetSymbolAddress((void**)&Ilo, g_Ilo);
    cudaGetSymbolAddress((void**)&IThi, g_IThi); cudaGetSymbolAddress((void**)&ITlo, g_ITlo);
    cudaGetSymbolAddress((void**)&wbhi, g_wbhi); cudaGetSymbolAddress((void**)&wblo, g_wblo);
    cudaGetSymbolAddress((void**)&wbThi, g_wbThi); cudaGetSymbolAddress((void**)&wbTlo, g_wbTlo);
    cudaGetSymbolAddress((void**)&wqThi, g_wqThi); cudaGetSymbolAddress((void**)&wqTlo, g_wqTlo);
    cudaGetSymbolAddress((void**)&wvThi, g_wvThi); cudaGetSymbolAddress((void**)&wvTlo, g_wvTlo);
    cudaGetSymbolAddress((void**)&wqqThi, g_wqqThi); cudaGetSymbolAddress((void**)&wqqTlo, g_wqqTlo);
    cudaGetSymbolAddress((void**)&wvvThi, g_wvvThi); cudaGetSymbolAddress((void**)&wvvTlo, g_wvvTlo);
    cudaGetSymbolAddress((void**)&A1Thi, g_A1Thi); cudaGetSymbolAddress((void**)&A1Tlo, g_A1Tlo);
    cudaGetSymbolAddress((void**)&M1Thi, g_M1Thi); cudaGetSymbolAddress((void**)&M1Tlo, g_M1Tlo);
    cudaGetSymbolAddress((void**)&A2Thi, g_A2Thi); cudaGetSymbolAddress((void**)&A2Tlo, g_A2Tlo);
    cudaGetSymbolAddress((void**)&HThi, g_HThi);   cudaGetSymbolAddress((void**)&HTlo, g_HTlo);
    cudaGetSymbolAddress((void**)&wqq, g_wqq);   cudaGetSymbolAddress((void**)&wvv, g_wvv);
    cudaGetSymbolAddress((void**)&wqqc, g_wqqc); cudaGetSymbolAddress((void**)&wvvc, g_wvvc);
    cudaGetSymbolAddress((void**)&sv, g_sv);     cudaGetSymbolAddress((void**)&sq, g_sq);
    cudaGetSymbolAddress((void**)&ctx, g_ctx);

    cudaFuncSetAttribute(mma_gemm<true, true>,
        cudaFuncAttributeMaxDynamicSharedMemorySize, SMEM_MMA_BYTES);
    cudaFuncSetAttribute(mma_gemm<false, true>,
        cudaFuncAttributeMaxDynamicSharedMemorySize, SMEM_MMA_BYTES);
    cudaFuncSetAttribute(mma_gemm<true, false>,
        cudaFuncAttributeMaxDynamicSharedMemorySize, SMEM_MMA_BYTES);

    const dim3 cblk(32, 8);

    // --- conversions ---
    conv_split<<<dim3(E / 32, LT / 32, Bn), cblk>>>(
        T, (long)LT * E, Thi, Tlo, (long)LT * E, TThi, TTlo, (long)E * LT, LT, E);
    conv_split<<<dim3(E / 32, LV / 32, Bn), cblk>>>(
        I, (long)LV * E, Ihi, Ilo, (long)LV * E, IThi, ITlo, (long)E * LV, LV, E);
    conv_split<<<dim3(E / 32, E / 32, 1), cblk>>>(
        wb, 0, wbhi, wblo, 0, wbThi, wbTlo, 0, E, E);
    conv_split<<<dim3(Kd / 32, E / 32, 1), cblk>>>(
        wq, 0, nullptr, nullptr, 0, wqThi, wqTlo, 0, E, Kd);
    conv_split<<<dim3(Kd / 32, E / 32, 1), cblk>>>(
        wv, 0, nullptr, nullptr, 0, wvThi, wvTlo, 0, E, Kd);

    // --- 8 GEMMs on tensor cores (HMMA) ---
    // 1) wqq = T @ w_q : flat M=B*LT, K=768; out f32 + C^T (RB=1024)
    mma_gemm<true, true><<<dim3((Bn * LT) / 128, 1, 1), 256, SMEM_MMA_BYTES>>>(
        Thi, Tlo, 0, wqThi, wqTlo, 0,
        wqq, 0, wqqThi, wqqTlo, 0, E, Bn * LT, LT);

    // 2) wvv = I @ w_v : flat M=B*LV; out f32 + C^T (RB=576)
    mma_gemm<true, true><<<dim3((Bn * LV) / 128, 1, 1), 256, SMEM_MMA_BYTES>>>(
        Ihi, Ilo, 0, wvThi, wvTlo, 0,
        wvv, 0, wvvThi, wvvTlo, 0, E, Bn * LV, LV);

    // 3) A1 = T^T @ wqq per batch: M=768, K=1024; out C^T
    mma_gemm<false, true><<<dim3(E / 128, 1, Bn), 256, SMEM_MMA_BYTES>>>(
        TThi, TTlo, (long)E * LT, wqqThi, wqqTlo, (long)Kd * LT,
        nullptr, 0, A1Thi, A1Tlo, (long)Kd * E, LT, E, E);

    // 4) M1 = w_b^T @ A1 per batch: M=768, K=768; out C^T
    mma_gemm<false, true><<<dim3(E / 128, 1, Bn), 256, SMEM_MMA_BYTES>>>(
        wbThi, wbTlo, 0, A1Thi, A1Tlo, (long)Kd * E,
        nullptr, 0, M1Thi, M1Tlo, (long)Kd * E, E, E, E);

    // 5) wqqc = I @ M1 per batch: M=576 (5 tiles, masked), K=768; out f32
    mma_gemm<true, false><<<dim3(5, 1, Bn), 256, SMEM_MMA_BYTES>>>(
        Ihi, Ilo, (long)LV * E, M1Thi, M1Tlo, (long)Kd * E,
        wqqc, (long)LV * Kd, nullptr, nullptr, 0, E, LV, LV);

    // 6) A2 = I^T @ wvv per batch: M=768, K=576; out C^T
    mma_gemm<false, true><<<dim3(E / 128, 1, Bn), 256, SMEM_MMA_BYTES>>>(
        IThi, ITlo, (long)E * LV, wvvThi, wvvTlo, (long)Kd * LV,
        nullptr, 0, A2Thi, A2Tlo, (long)Kd * E, LV, E, E);

    // 7) H = w_b @ A2 per batch: M=768, K=768; out C^T
    mma_gemm<false, true><<<dim3(E / 128, 1, Bn), 256, SMEM_MMA_BYTES>>>(
        wbhi, wblo, 0, A2Thi, A2Tlo, (long)Kd * E,
        nullptr, 0, HThi, HTlo, (long)Kd * E, E, E, E);

    // 8) wvvc = T @ H per batch: M=1024, K=768; out f32
    mma_gemm<true, false><<<dim3(LT / 128, 1, Bn), 256, SMEM_MMA_BYTES>>>(
        Thi, Tlo, (long)LT * E, HThi, HTlo, (long)Kd * E,
        wvvc, (long)LT * Kd, nullptr, nullptr, 0, E, LT, LT);

    // --- scores / softmax / context / output ---
    {
        int total_v = Bn * LV;
        int total_q = Bn * LT;
        score_kernel<<<(total_v * 32 + 255) / 256, 256>>>(wvv, wqqc, whv, sv, total_v);
        score_kernel<<<(total_q * 32 + 255) / 256, 256>>>(wqq, wvvc, whq, sq, total_q);
    }
    softmax_kernel<<<Bn, 256>>>(sv, LV);
    softmax_kernel<<<Bn, 256>>>(sq, LT);
    context_kernel<<<Bn, 768>>>(T, I, sq, sv, ctx);
    out_kernel<<<Bn, 768>>>(ctx, ws, out);
}

// round 5
// speedup vs baseline: 1.8126x; 1.3259x over previous
#include <cuda_runtime.h>
#include <cuda_bf16.h>
#include <math.h>
#include <stdint.h>

// Problem constants: B=64, LT=1024, LV=576, E=768, K=128
namespace cfg {
constexpr int Bn = 64;
constexpr int LT = 1024;
constexpr int LV = 576;
constexpr int E  = 768;
constexpr int Kd = 128;
}
using bf16 = __nv_bfloat16;

__device__ __forceinline__ void split2(float v, bf16& h, bf16& l) {
    h = __float2bfloat16(v);
    l = __float2bfloat16(v - __bfloat162float(h));
}

__device__ __forceinline__ void mma16816(float* d, const uint32_t* a, const uint32_t* b) {
    asm volatile(
        "mma.sync.aligned.m16n8k16.row.col.f32.bf16.bf16.f32 "
        "{%0,%1,%2,%3}, {%4,%5,%6,%7}, {%8,%9}, {%0,%1,%2,%3};"
        : "+f"(d[0]), "+f"(d[1]), "+f"(d[2]), "+f"(d[3])
        : "r"(a[0]), "r"(a[1]), "r"(a[2]), "r"(a[3]), "r"(b[0]), "r"(b[1]));
}

__device__ __forceinline__ void ldm_x4(uint32_t* r, uint32_t saddr) {
    asm volatile("ldmatrix.sync.aligned.m8n8.x4.shared.b16 {%0,%1,%2,%3}, [%4];"
        : "=r"(r[0]), "=r"(r[1]), "=r"(r[2]), "=r"(r[3]) : "r"(saddr));
}

__device__ __forceinline__ uint32_t smem_u32(const void* p) {
    uint32_t a;
    asm("{ .reg .u64 t; cvta.to.shared.u64 t, %1; cvt.u32.u64 %0, t; }"
        : "=r"(a) : "l"(p));
    return a;
}

#define CP_ASYNC16(s, g) \
    asm volatile("cp.async.cg.shared.global [%0], [%1], 16;" :: "r"(s), "l"(g))
#define CP_COMMIT() asm volatile("cp.async.commit_group;")
#define CP_WAIT1()  asm volatile("cp.async.wait_group 1;")
#define CP_WAIT0()  asm volatile("cp.async.wait_group 0;")

// ===========================================================================
// Scratch (device globals)
// ===========================================================================
#define DEV_BF16(name, n) __device__ __align__(256) bf16 name[n]
DEV_BF16(g_Thi,  64 * 1024 * 768);
DEV_BF16(g_Tlo,  64 * 1024 * 768);
DEV_BF16(g_TThi, 64 * 768 * 1024);
DEV_BF16(g_TTlo, 64 * 768 * 1024);
DEV_BF16(g_Ihi,  64 * 576 * 768 + 64 * 768);   // +pad: call5 reads 64 extra rows
DEV_BF16(g_Ilo,  64 * 576 * 768 + 64 * 768);
DEV_BF16(g_IThi, 64 * 768 * 576);
DEV_BF16(g_ITlo, 64 * 768 * 576);
DEV_BF16(g_wbhi,  768 * 768);
DEV_BF16(g_wblo,  768 * 768);
DEV_BF16(g_wbThi, 768 * 768);
DEV_BF16(g_wbTlo, 768 * 768);
DEV_BF16(g_wqThi, 128 * 768);
DEV_BF16(g_wqTlo, 128 * 768);
DEV_BF16(g_wvThi, 128 * 768);
DEV_BF16(g_wvTlo, 128 * 768);
DEV_BF16(g_wqqThi, 64 * 128 * 1024);
DEV_BF16(g_wqqTlo, 64 * 128 * 1024);
DEV_BF16(g_wvvThi, 64 * 128 * 576);
DEV_BF16(g_wvvTlo, 64 * 128 * 576);
DEV_BF16(g_A1Thi, 64 * 128 * 768);
DEV_BF16(g_A1Tlo, 64 * 128 * 768);
DEV_BF16(g_M1Thi, 64 * 128 * 768);
DEV_BF16(g_M1Tlo, 64 * 128 * 768);
DEV_BF16(g_A2Thi, 64 * 128 * 768);
DEV_BF16(g_A2Tlo, 64 * 128 * 768);
DEV_BF16(g_HThi,  64 * 128 * 768);
DEV_BF16(g_HTlo,  64 * 128 * 768);

__device__ float g_wqq [cfg::Bn * cfg::LT * cfg::Kd];
__device__ float g_wvv [cfg::Bn * cfg::LV * cfg::Kd];
__device__ float g_wqqc[cfg::Bn * cfg::LV * cfg::Kd];
__device__ float g_wvvc[cfg::Bn * cfg::LT * cfg::Kd];
__device__ float g_sv  [cfg::Bn * cfg::LV];
__device__ float g_sq  [cfg::Bn * cfg::LT];
__device__ float g_ctx [cfg::Bn * cfg::E];

// ===========================================================================
// Conversion: fp32 [z][R,C] -> bf16 hi/lo [z][R,C] and/or transposed [z][C,R]
// ===========================================================================
__global__ void conv_split(const float* __restrict__ X, long sX,
                           bf16* hi, bf16* lo, long sHL,
                           bf16* hiT, bf16* loT, long sT,
                           int R, int C)
{
    __shared__ float tile[32][33];
    const float* Xb = X + (long)blockIdx.z * sX;
    const int c0 = blockIdx.x * 32, r0 = blockIdx.y * 32;
    const int tx = threadIdx.x, ty = threadIdx.y;
#pragma unroll
    for (int j = 0; j < 4; j++) {
        int r = r0 + ty + j * 8;
        float v = Xb[(long)r * C + c0 + tx];
        tile[ty + j * 8][tx] = v;
        if (hi) {
            bf16 h, l; split2(v, h, l);
            long o = (long)blockIdx.z * sHL + (long)r * C + c0 + tx;
            hi[o] = h; lo[o] = l;
        }
    }
    __syncthreads();
    if (hiT) {
#pragma unroll
        for (int j = 0; j < 4; j++) {
            int cc = c0 + ty + j * 8;
            int rr = r0 + tx;
            float v = tile[tx][ty + j * 8];
            bf16 h, l; split2(v, h, l);
            long o = (long)blockIdx.z * sT + (long)cc * R + rr;
            hiT[o] = h; loT[o] = l;
        }
    }
}

// ===========================================================================
// HMMA batched GEMM with ldmatrix + cp.async: C[M,128] = A[M,K] @ B[K,128]
// (fp32 via bf16x3 split). See Round 4 comments for layout contracts.
// ===========================================================================
constexpr int PAD  = 40;                   // bf16 per smem row (conflict-free)
constexpr int PADB = PAD * 2;              // bytes
constexpr int MATB = 128 * PADB;           // 10240 B per matrix tile
constexpr int STAGEB = 4 * MATB;           // 40960 B (Ah, Al, Bh, Bl)
static constexpr int SMEM_MMA_BYTES = 2 * STAGEB;   // 81920 B

template <bool OUTF, bool OUTT>
__global__ void __launch_bounds__(256, 2) mma_gemm(
    const bf16* __restrict__ Ahi, const bf16* __restrict__ Alo, long sA,
    const bf16* __restrict__ Bhi, const bf16* __restrict__ Blo, long sB,
    float* __restrict__ Cf, long sC,
    bf16* __restrict__ CThi, bf16* __restrict__ CTlo, long sCT,
    int Ktot, int Mvalid, int RB)
{
    extern __shared__ __align__(16) bf16 sm[];
    const uint32_t smb = smem_u32(sm);

    const int tid  = threadIdx.x;
    const int lane = tid & 31;
    const int wid  = tid >> 5;
    const int wm   = wid & 1;    // 0..1
    const int wn   = wid >> 1;   // 0..3
    const int g    = lane >> 2;  // 0..7
    const int t    = lane & 3;   // 0..3

    const long z  = blockIdx.z;
    const int  m0 = blockIdx.x * 128;

    const bf16* Ah = Ahi + z * sA + (long)m0 * Ktot;
    const bf16* Al = Alo + z * sA + (long)m0 * Ktot;
    const bf16* Bh = Bhi + z * sB;
    const bf16* Bl = Blo + z * sB;

    float acc[4][4][4];
#pragma unroll
    for (int i = 0; i < 4; i++)
#pragma unroll
        for (int j = 0; j < 4; j++)
#pragma unroll
            for (int q = 0; q < 4; q++) acc[i][j][q] = 0.f;

    const int nch = Ktot >> 5;

    // per-thread load coordinates (2 x 16B per tile)
    const int lrow0 = (tid * 2)     >> 2, lc0 = (tid * 2)     & 3;
    const int lrow1 = (tid * 2 + 1) >> 2, lc1 = (tid * 2 + 1) & 3;

    auto load_chunk = [&](int c, int stage) {
        const int k0 = c << 5;
        const bf16* srcs[4] = {Ah, Al, Bh, Bl};
        const uint32_t sb = smb + stage * STAGEB;
#pragma unroll
        for (int mt = 0; mt < 4; mt++) {
            const bf16* src = srcs[mt];
            const uint32_t dst = sb + mt * MATB;
            CP_ASYNC16(dst + lrow0 * PADB + lc0 * 16,
                       src + (long)lrow0 * Ktot + k0 + lc0 * 8);
            CP_ASYNC16(dst + lrow1 * PADB + lc1 * 16,
                       src + (long)lrow1 * Ktot + k0 + lc1 * 8);
        }
    };

    // ldmatrix lane-derived offsets
    const int aRow   = (lane & 7) + ((lane >> 3) & 1) * 8;  // row within 16
    const int aKhalf = (lane >> 4) * 8;                     // 0 or 8 (bf16)
    const int bQ     = lane >> 3;                           // 0..3
    const int bNf    = bQ >> 1;                             // 0..1 (nf offset)
    const int bKhalf = (bQ & 1) * 8;
    const int bRow   = lane & 7;

    auto compute_chunk = [&](int stage) {
        const uint32_t sb   = smb + stage * STAGEB;
        const uint32_t pAh  = sb + (wm * 64) * PADB;
        const uint32_t pAl  = pAh + MATB;
        const uint32_t pBh  = sb + 2 * MATB + (wn * 32) * PADB;
        const uint32_t pBl  = pBh + MATB;
#pragma unroll
        for (int ks = 0; ks < 2; ks++) {
            const int kc0 = ks * 32;   // bytes: ks*16 bf16
            uint32_t bh[4][2], bl[4][2];
#pragma unroll
            for (int nfb = 0; nfb < 4; nfb += 2) {
                uint32_t r[4];
                uint32_t addr = pBh + ((nfb + bNf) * 8 + bRow) * PADB + kc0 + bKhalf * 2;
                ldm_x4(r, addr);
                bh[nfb][0] = r[0]; bh[nfb][1] = r[1];
                bh[nfb + 1][0] = r[2]; bh[nfb + 1][1] = r[3];
                addr = pBl + ((nfb + bNf) * 8 + bRow) * PADB + kc0 + bKhalf * 2;
                ldm_x4(r, addr);
                bl[nfb][0] = r[0]; bl[nfb][1] = r[1];
                bl[nfb + 1][0] = r[2]; bl[nfb + 1][1] = r[3];
            }
#pragma unroll
            for (int mf = 0; mf < 4; mf++) {
                uint32_t ah[4], al[4];
                ldm_x4(ah, pAh + (mf * 16 + aRow) * PADB + kc0 + aKhalf * 2);
                ldm_x4(al, pAl + (mf * 16 + aRow) * PADB + kc0 + aKhalf * 2);
#pragma unroll
                for (int nf = 0; nf < 4; nf++) {
                    mma16816(acc[mf][nf], ah, bh[nf]);   // hi*hi
                    mma16816(acc[mf][nf], ah, bl[nf]);   // hi*lo
                    mma16816(acc[mf][nf], al, bh[nf]);   // lo*hi
                }
            }
        }
    };

    load_chunk(0, 0);
    CP_COMMIT();
    for (int c = 0; c < nch; c++) {
        if (c + 1 < nch) {
            load_chunk(c + 1, (c + 1) & 1);
            CP_COMMIT();
            CP_WAIT1();
        } else {
            CP_WAIT0();
        }
        __syncthreads();
        compute_chunk(c & 1);
        __syncthreads();
    }

    // epilogue
#pragma unroll
    for (int mf = 0; mf < 4; mf++) {
#pragma unroll
        for (int nf = 0; nf < 4; nf++) {
            const int mr0 = m0 + wm * 64 + mf * 16 + g;
            const int mr1 = mr0 + 8;
            const int n0  = wn * 32 + nf * 8 + 2 * t;
            const float* cc = acc[mf][nf];
            if (OUTF) {
                if (mr0 < Mvalid)
                    *(float2*)(Cf + z * sC + (long)mr0 * 128 + n0) =
                        make_float2(cc[0], cc[1]);
                if (mr1 < Mvalid)
                    *(float2*)(Cf + z * sC + (long)mr1 * 128 + n0) =
                        make_float2(cc[2], cc[3]);
            }
            if (OUTT) {
#pragma unroll
                for (int q = 0; q < 4; q++) {
                    const int m = (q < 2) ? mr0 : mr1;
                    const int n = n0 + (q & 1);
                    if (m < Mvalid) {
                        const long bb = m / RB, ml = m % RB;
                        bf16 h, l; split2(cc[q], h, l);
                        const long o = z * sCT + bb * (128L * RB) + (long)n * RB + ml;
                        CThi[o] = h;
                        CTlo[o] = l;
                    }
                }
            }
        }
    }
}

// ===========================================================================
// Elementwise tail
// ===========================================================================
__global__ void score_kernel(const float* __restrict__ U,
                             const float* __restrict__ Vc,
                             const float* __restrict__ wh,
                             float* __restrict__ s, int total)
{
    int gw   = (blockIdx.x * blockDim.x + threadIdx.x) >> 5;
    int lane = threadIdx.x & 31;
    if (gw >= total) return;
    const float* u = U  + (long)gw * 128;
    const float* v = Vc + (long)gw * 128;
    float acc = 0.f;
#pragma unroll
    for (int k = 0; k < 4; k++) {
        int idx = lane + 32 * k;
        acc += tanhf(u[idx] + v[idx]) * wh[idx];
    }
#pragma unroll
    for (int o = 16; o > 0; o >>= 1)
        acc += __shfl_xor_sync(0xffffffffu, acc, o);
    if (lane == 0) s[gw] = acc;
}

__global__ void softmax_kernel(float* __restrict__ s, int L)
{
    float* row = s + (long)blockIdx.x * L;
    __shared__ float red[32];
    __shared__ float bval;
    const int tid  = threadIdx.x;
    const int lane = tid & 31;
    const int wid  = tid >> 5;
    const int nw   = blockDim.x >> 5;

    float m = -1e30f;
    for (int i = tid; i < L; i += blockDim.x) m = fmaxf(m, row[i]);
#pragma unroll
    for (int o = 16; o > 0; o >>= 1) m = fmaxf(m, __shfl_xor_sync(0xffffffffu, m, o));
    if (lane == 0) red[wid] = m;
    __syncthreads();
    if (tid == 0) {
        float mm = red[0];
        for (int w = 1; w < nw; w++) mm = fmaxf(mm, red[w]);
        bval = mm;
    }
    __syncthreads();
    m = bval;
    __syncthreads();

    float sum = 0.f;
    for (int i = tid; i < L; i += blockDim.x) {
        float e = expf(row[i] - m);
        row[i] = e;
        sum += e;
    }
#pragma unroll
    for (int o = 16; o > 0; o >>= 1) sum += __shfl_xor_sync(0xffffffffu, sum, o);
    if (lane == 0) red[wid] = sum;
    __syncthreads();
    if (tid == 0) {
        float ss = 0.f;
        for (int w = 0; w < nw; w++) ss += red[w];
        bval = ss;
    }
    __syncthreads();
    float inv = 1.f / bval;
    for (int i = tid; i < L; i += blockDim.x) row[i] *= inv;
}

__global__ void __launch_bounds__(768) context_kernel(
    const float* __restrict__ T, const float* __restrict__ I,
    const float* __restrict__ aq, const float* __restrict__ av,
    float* __restrict__ ctx)
{
    __shared__ float sq[cfg::LT];
    __shared__ float sv[cfg::LV];
    const int b = blockIdx.x;
    const int d = threadIdx.x;
    for (int i = d; i < cfg::LT; i += 768) sq[i] = aq[(long)b * cfg::LT + i];
    if (d < cfg::LV) sv[d] = av[(long)b * cfg::LV + d];
    __syncthreads();

    const float* Ib = I + (long)b * cfg::LV * cfg::E + d;
    const float* Tb = T + (long)b * cfg::LT * cfg::E + d;
    float acc = 0.f;
#pragma unroll 4
    for (int y = 0; y < cfg::LV; y++) acc += sv[y] * Ib[(long)y * cfg::E];
#pragma unroll 4
    for (int x = 0; x < cfg::LT; x++) acc += sq[x] * Tb[(long)x * cfg::E];
    ctx[(long)b * cfg::E + d] = acc;
}

__global__ void __launch_bounds__(768) out_kernel(
    const float* __restrict__ ctx, const float* __restrict__ ws,
    float* __restrict__ out)
{
    __shared__ float sc[cfg::E];
    const int b = blockIdx.x;
    const int e = threadIdx.x;
    sc[e] = ctx[(long)b * cfg::E + e];
    __syncthreads();
    float acc = 0.f;
#pragma unroll 8
    for (int d = 0; d < cfg::E; d++)
        acc += sc[d] * ws[(long)d * cfg::E + e];
    out[(long)b * cfg::E + e] = tanhf(acc);
}

// ===========================================================================
// launch
// ===========================================================================
extern "C" void kernel_launch(void* const* d_in, const int* in_sizes, int n_in,
                              void* d_out, int out_size)
{
    using namespace cfg;
    const float* T   = (const float*)d_in[0];
    const float* I   = (const float*)d_in[1];
    const float* wb  = (const float*)d_in[3];
    const float* wv  = (const float*)d_in[4];
    const float* wq  = (const float*)d_in[5];
    const float* whv = (const float*)d_in[6];
    const float* whq = (const float*)d_in[7];
    const float* ws  = (const float*)d_in[8];
    float* out = (float*)d_out;

    bf16 *Thi, *Tlo, *TThi, *TTlo, *Ihi, *Ilo, *IThi, *ITlo;
    bf16 *wbhi, *wblo, *wbThi, *wbTlo, *wqThi, *wqTlo, *wvThi, *wvTlo;
    bf16 *wqqThi, *wqqTlo, *wvvThi, *wvvTlo;
    bf16 *A1Thi, *A1Tlo, *M1Thi, *M1Tlo, *A2Thi, *A2Tlo, *HThi, *HTlo;
    float *wqq, *wvv, *wqqc, *wvvc, *sv, *sq, *ctx;

    cudaGetSymbolAddress((void**)&Thi, g_Thi);   cudaGetSymbolAddress((void**)&Tlo, g_Tlo);
    cudaGetSymbolAddress((void**)&TThi, g_TThi); cudaGetSymbolAddress((void**)&TTlo, g_TTlo);
    cudaGetSymbolAddress((void**)&Ihi, g_Ihi);   cudaGetSymbolAddress((void**)&Ilo, g_Ilo);
    cudaGetSymbolAddress((void**)&IThi, g_IThi); cudaGetSymbolAddress((void**)&ITlo, g_ITlo);
    cudaGetSymbolAddress((void**)&wbhi, g_wbhi); cudaGetSymbolAddress((void**)&wblo, g_wblo);
    cudaGetSymbolAddress((void**)&wbThi, g_wbThi); cudaGetSymbolAddress((void**)&wbTlo, g_wbTlo);
    cudaGetSymbolAddress((void**)&wqThi, g_wqThi); cudaGetSymbolAddress((void**)&wqTlo, g_wqTlo);
    cudaGetSymbolAddress((void**)&wvThi, g_wvThi); cudaGetSymbolAddress((void**)&wvTlo, g_wvTlo);
    cudaGetSymbolAddress((void**)&wqqThi, g_wqqThi); cudaGetSymbolAddress((void**)&wqqTlo, g_wqqTlo);
    cudaGetSymbolAddress((void**)&wvvThi, g_wvvThi); cudaGetSymbolAddress((void**)&wvvTlo, g_wvvTlo);
    cudaGetSymbolAddress((void**)&A1Thi, g_A1Thi); cudaGetSymbolAddress((void**)&A1Tlo, g_A1Tlo);
    cudaGetSymbolAddress((void**)&M1Thi, g_M1Thi); cudaGetSymbolAddress((void**)&M1Tlo, g_M1Tlo);
    cudaGetSymbolAddress((void**)&A2Thi, g_A2Thi); cudaGetSymbolAddress((void**)&A2Tlo, g_A2Tlo);
    cudaGetSymbolAddress((void**)&HThi, g_HThi);   cudaGetSymbolAddress((void**)&HTlo, g_HTlo);
    cudaGetSymbolAddress((void**)&wqq, g_wqq);   cudaGetSymbolAddress((void**)&wvv, g_wvv);
    cudaGetSymbolAddress((void**)&wqqc, g_wqqc); cudaGetSymbolAddress((void**)&wvvc, g_wvvc);
    cudaGetSymbolAddress((void**)&sv, g_sv);     cudaGetSymbolAddress((void**)&sq, g_sq);
    cudaGetSymbolAddress((void**)&ctx, g_ctx);

    cudaFuncSetAttribute(mma_gemm<true, true>,
        cudaFuncAttributeMaxDynamicSharedMemorySize, SMEM_MMA_BYTES);
    cudaFuncSetAttribute(mma_gemm<false, true>,
        cudaFuncAttributeMaxDynamicSharedMemorySize, SMEM_MMA_BYTES);
    cudaFuncSetAttribute(mma_gemm<true, false>,
        cudaFuncAttributeMaxDynamicSharedMemorySize, SMEM_MMA_BYTES);

    const dim3 cblk(32, 8);

    // --- conversions ---
    conv_split<<<dim3(E / 32, LT / 32, Bn), cblk>>>(
        T, (long)LT * E, Thi, Tlo, (long)LT * E, TThi, TTlo, (long)E * LT, LT, E);
    conv_split<<<dim3(E / 32, LV / 32, Bn), cblk>>>(
        I, (long)LV * E, Ihi, Ilo, (long)LV * E, IThi, ITlo, (long)E * LV, LV, E);
    conv_split<<<dim3(E / 32, E / 32, 1), cblk>>>(
        wb, 0, wbhi, wblo, 0, wbThi, wbTlo, 0, E, E);
    conv_split<<<dim3(Kd / 32, E / 32, 1), cblk>>>(
        wq, 0, nullptr, nullptr, 0, wqThi, wqTlo, 0, E, Kd);
    conv_split<<<dim3(Kd / 32, E / 32, 1), cblk>>>(
        wv, 0, nullptr, nullptr, 0, wvThi, wvTlo, 0, E, Kd);

    // --- 8 GEMMs on tensor cores (HMMA + ldmatrix + cp.async) ---
    mma_gemm<true, true><<<dim3((Bn * LT) / 128, 1, 1), 256, SMEM_MMA_BYTES>>>(
        Thi, Tlo, 0, wqThi, wqTlo, 0,
        wqq, 0, wqqThi, wqqTlo, 0, E, Bn * LT, LT);

    mma_gemm<true, true><<<dim3((Bn * LV) / 128, 1, 1), 256, SMEM_MMA_BYTES>>>(
        Ihi, Ilo, 0, wvThi, wvTlo, 0,
        wvv, 0, wvvThi, wvvTlo, 0, E, Bn * LV, LV);

    mma_gemm<false, true><<<dim3(E / 128, 1, Bn), 256, SMEM_MMA_BYTES>>>(
        TThi, TTlo, (long)E * LT, wqqThi, wqqTlo, (long)Kd * LT,
        nullptr, 0, A1Thi, A1Tlo, (long)Kd * E, LT, E, E);

    mma_gemm<false, true><<<dim3(E / 128, 1, Bn), 256, SMEM_MMA_BYTES>>>(
        wbThi, wbTlo, 0, A1Thi, A1Tlo, (long)Kd * E,
        nullptr, 0, M1Thi, M1Tlo, (long)Kd * E, E, E, E);

    mma_gemm<true, false><<<dim3(5, 1, Bn), 256, SMEM_MMA_BYTES>>>(
        Ihi, Ilo, (long)LV * E, M1Thi, M1Tlo, (long)Kd * E,
        wqqc, (long)LV * Kd, nullptr, nullptr, 0, E, LV, LV);

    mma_gemm<false, true><<<dim3(E / 128, 1, Bn), 256, SMEM_MMA_BYTES>>>(
        IThi, ITlo, (long)E * LV, wvvThi, wvvTlo, (long)Kd * LV,
        nullptr, 0, A2Thi, A2Tlo, (long)Kd * E, LV, E, E);

    mma_gemm<false, true><<<dim3(E / 128, 1, Bn), 256, SMEM_MMA_BYTES>>>(
        wbhi, wblo, 0, A2Thi, A2Tlo, (long)Kd * E,
        nullptr, 0, HThi, HTlo, (long)Kd * E, E, E, E);

    mma_gemm<true, false><<<dim3(LT / 128, 1, Bn), 256, SMEM_MMA_BYTES>>>(
        Thi, Tlo, (long)LT * E, HThi, HTlo, (long)Kd * E,
        wvvc, (long)LT * Kd, nullptr, nullptr, 0, E, LT, LT);

    // --- scores / softmax / context / output ---
    {
        int total_v = Bn * LV;
        int total_q = Bn * LT;
        score_kernel<<<(total_v * 32 + 255) / 256, 256>>>(wvv, wqqc, whv, sv, total_v);
        score_kernel<<<(total_q * 32 + 255) / 256, 256>>>(wqq, wvvc, whq, sq, total_q);
    }
    softmax_kernel<<<Bn, 256>>>(sv, LV);
    softmax_kernel<<<Bn, 256>>>(sq, LT);
    context_kernel<<<Bn, 768>>>(T, I, sq, sv, ctx);
    out_kernel<<<Bn, 768>>>(ctx, ws, out);
}

// round 6
// speedup vs baseline: 1.9203x; 1.0594x over previous
#include <cuda_runtime.h>
#include <cuda_bf16.h>
#include <math.h>
#include <stdint.h>

// Problem constants: B=64, LT=1024, LV=576, E=768, K=128
namespace cfg {
constexpr int Bn = 64;
constexpr int LT = 1024;
constexpr int LV = 576;
constexpr int E  = 768;
constexpr int Kd = 128;
}
using bf16 = __nv_bfloat16;

__device__ __forceinline__ void split2(float v, bf16& h, bf16& l) {
    h = __float2bfloat16(v);
    l = __float2bfloat16(v - __bfloat162float(h));
}

__device__ __forceinline__ void mma16816(float* d, const uint32_t* a, const uint32_t* b) {
    asm volatile(
        "mma.sync.aligned.m16n8k16.row.col.f32.bf16.bf16.f32 "
        "{%0,%1,%2,%3}, {%4,%5,%6,%7}, {%8,%9}, {%0,%1,%2,%3};"
        : "+f"(d[0]), "+f"(d[1]), "+f"(d[2]), "+f"(d[3])
        : "r"(a[0]), "r"(a[1]), "r"(a[2]), "r"(a[3]), "r"(b[0]), "r"(b[1]));
}

__device__ __forceinline__ void ldm_x4(uint32_t* r, uint32_t saddr) {
    asm volatile("ldmatrix.sync.aligned.m8n8.x4.shared.b16 {%0,%1,%2,%3}, [%4];"
        : "=r"(r[0]), "=r"(r[1]), "=r"(r[2]), "=r"(r[3]) : "r"(saddr));
}

__device__ __forceinline__ uint32_t smem_u32(const void* p) {
    uint32_t a;
    asm("{ .reg .u64 t; cvta.to.shared.u64 t, %1; cvt.u32.u64 %0, t; }"
        : "=r"(a) : "l"(p));
    return a;
}

#define CP_ASYNC16(s, g) \
    asm volatile("cp.async.cg.shared.global [%0], [%1], 16;" :: "r"(s), "l"(g))
#define CP_COMMIT() asm volatile("cp.async.commit_group;")
#define CP_WAIT1()  asm volatile("cp.async.wait_group 1;")
#define CP_WAIT0()  asm volatile("cp.async.wait_group 0;")

// ===========================================================================
// Scratch (device globals)
// ===========================================================================
#define DEV_BF16(name, n) __device__ __align__(256) bf16 name[n]
DEV_BF16(g_Thi,  64 * 1024 * 768);
DEV_BF16(g_Tlo,  64 * 1024 * 768);
DEV_BF16(g_TThi, 64 * 768 * 1024);
DEV_BF16(g_TTlo, 64 * 768 * 1024);
DEV_BF16(g_Ihi,  64 * 576 * 768 + 64 * 768);   // +pad: GEMM5 reads 64 extra rows
DEV_BF16(g_Ilo,  64 * 576 * 768 + 64 * 768);
DEV_BF16(g_IThi, 64 * 768 * 576);
DEV_BF16(g_ITlo, 64 * 768 * 576);
DEV_BF16(g_wbhi,  768 * 768);
DEV_BF16(g_wblo,  768 * 768);
DEV_BF16(g_wbThi, 768 * 768);
DEV_BF16(g_wbTlo, 768 * 768);
DEV_BF16(g_wqThi, 128 * 768);
DEV_BF16(g_wqTlo, 128 * 768);
DEV_BF16(g_wvThi, 128 * 768);
DEV_BF16(g_wvTlo, 128 * 768);
DEV_BF16(g_wqqThi, 64 * 128 * 1024);
DEV_BF16(g_wqqTlo, 64 * 128 * 1024);
DEV_BF16(g_wvvThi, 64 * 128 * 576);
DEV_BF16(g_wvvTlo, 64 * 128 * 576);
DEV_BF16(g_A1Thi, 64 * 128 * 768);
DEV_BF16(g_A1Tlo, 64 * 128 * 768);
DEV_BF16(g_M1Thi, 64 * 128 * 768);
DEV_BF16(g_M1Tlo, 64 * 128 * 768);
DEV_BF16(g_A2Thi, 64 * 128 * 768);
DEV_BF16(g_A2Tlo, 64 * 128 * 768);
DEV_BF16(g_HThi,  64 * 128 * 768);
DEV_BF16(g_HTlo,  64 * 128 * 768);

__device__ float g_wqq [cfg::Bn * cfg::LT * cfg::Kd];
__device__ float g_wvv [cfg::Bn * cfg::LV * cfg::Kd];
__device__ float g_wqqc[cfg::Bn * cfg::LV * cfg::Kd];
__device__ float g_wvvc[cfg::Bn * cfg::LT * cfg::Kd];
__device__ float g_sv  [cfg::Bn * cfg::LV];
__device__ float g_sq  [cfg::Bn * cfg::LT];
__device__ float g_ctx [cfg::Bn * cfg::E];

// ===========================================================================
// Conversion: fp32 [z][R,C] -> bf16 hi/lo [z][R,C] and/or transposed [z][C,R]
// ===========================================================================
__global__ void conv_split(const float* __restrict__ X, long sX,
                           bf16* hi, bf16* lo, long sHL,
                           bf16* hiT, bf16* loT, long sT,
                           int R, int C)
{
    __shared__ float tile[32][33];
    const float* Xb = X + (long)blockIdx.z * sX;
    const int c0 = blockIdx.x * 32, r0 = blockIdx.y * 32;
    const int tx = threadIdx.x, ty = threadIdx.y;
#pragma unroll
    for (int j = 0; j < 4; j++) {
        int r = r0 + ty + j * 8;
        float v = Xb[(long)r * C + c0 + tx];
        tile[ty + j * 8][tx] = v;
        if (hi) {
            bf16 h, l; split2(v, h, l);
            long o = (long)blockIdx.z * sHL + (long)r * C + c0 + tx;
            hi[o] = h; lo[o] = l;
        }
    }
    __syncthreads();
    if (hiT) {
#pragma unroll
        for (int j = 0; j < 4; j++) {
            int cc = c0 + ty + j * 8;
            int rr = r0 + tx;
            float v = tile[tx][ty + j * 8];
            bf16 h, l; split2(v, h, l);
            long o = (long)blockIdx.z * sT + (long)cc * R + rr;
            hiT[o] = h; loT[o] = l;
        }
    }
}

// ===========================================================================
// Merged-pair HMMA batched GEMM.  C[M,128] = A[M,K] @ B[K,128] (bf16x3 split)
// Two independent GEMMs per launch, selected by blockIdx.x < splitX.
// OUTT epilogue stages C through smem for fully coalesced bf16 stores.
// ===========================================================================
constexpr int PAD  = 40;                   // bf16 per smem row (conflict-free)
constexpr int PADB = PAD * 2;
constexpr int MATB = 128 * PADB;           // 10240 B
constexpr int STAGEB = 4 * MATB;           // 40960 B
static constexpr int SMEM_MMA_BYTES = 2 * STAGEB;   // 81920 B

struct GArgs {
    const bf16 *Ahi, *Alo, *Bhi, *Blo;
    long sA, sB, sC, sCT;
    float* Cf;
    bf16 *CThi, *CTlo;
    int Ktot, Mvalid, RB;
};

template <bool OUTF, bool OUTT>
__global__ void __launch_bounds__(256, 2) mma_gemm(GArgs a0, GArgs a1, int splitX)
{
    extern __shared__ __align__(16) bf16 sm[];
    const uint32_t smb = smem_u32(sm);

    const GArgs& A = (blockIdx.x < (unsigned)splitX) ? a0 : a1;
    const int bx = (blockIdx.x < (unsigned)splitX) ? blockIdx.x
                                                   : blockIdx.x - splitX;

    const int tid  = threadIdx.x;
    const int lane = tid & 31;
    const int wid  = tid >> 5;
    const int wm   = wid & 1;
    const int wn   = wid >> 1;
    const int g    = lane >> 2;
    const int t    = lane & 3;

    const long z  = blockIdx.z;
    const int  m0 = bx * 128;
    const int  Ktot = A.Ktot;

    const bf16* Ah = A.Ahi + z * A.sA + (long)m0 * Ktot;
    const bf16* Al = A.Alo + z * A.sA + (long)m0 * Ktot;
    const bf16* Bh = A.Bhi + z * A.sB;
    const bf16* Bl = A.Blo + z * A.sB;

    float acc[4][4][4];
#pragma unroll
    for (int i = 0; i < 4; i++)
#pragma unroll
        for (int j = 0; j < 4; j++)
#pragma unroll
            for (int q = 0; q < 4; q++) acc[i][j][q] = 0.f;

    const int nch = Ktot >> 5;

    const int lrow0 = (tid * 2)     >> 2, lc0 = (tid * 2)     & 3;
    const int lrow1 = (tid * 2 + 1) >> 2, lc1 = (tid * 2 + 1) & 3;

    auto load_chunk = [&](int c, int stage) {
        const int k0 = c << 5;
        const bf16* srcs[4] = {Ah, Al, Bh, Bl};
        const uint32_t sb = smb + stage * STAGEB;
#pragma unroll
        for (int mt = 0; mt < 4; mt++) {
            const bf16* src = srcs[mt];
            const uint32_t dst = sb + mt * MATB;
            CP_ASYNC16(dst + lrow0 * PADB + lc0 * 16,
                       src + (long)lrow0 * Ktot + k0 + lc0 * 8);
            CP_ASYNC16(dst + lrow1 * PADB + lc1 * 16,
                       src + (long)lrow1 * Ktot + k0 + lc1 * 8);
        }
    };

    const int aRow   = (lane & 7) + ((lane >> 3) & 1) * 8;
    const int aKhalf = (lane >> 4) * 8;
    const int bQ     = lane >> 3;
    const int bNf    = bQ >> 1;
    const int bKhalf = (bQ & 1) * 8;
    const int bRow   = lane & 7;

    auto compute_chunk = [&](int stage) {
        const uint32_t sb   = smb + stage * STAGEB;
        const uint32_t pAh  = sb + (wm * 64) * PADB;
        const uint32_t pAl  = pAh + MATB;
        const uint32_t pBh  = sb + 2 * MATB + (wn * 32) * PADB;
        const uint32_t pBl  = pBh + MATB;
#pragma unroll
        for (int ks = 0; ks < 2; ks++) {
            const int kc0 = ks * 32;
            uint32_t bh[4][2], bl[4][2];
#pragma unroll
            for (int nfb = 0; nfb < 4; nfb += 2) {
                uint32_t r[4];
                uint32_t addr = pBh + ((nfb + bNf) * 8 + bRow) * PADB + kc0 + bKhalf * 2;
                ldm_x4(r, addr);
                bh[nfb][0] = r[0]; bh[nfb][1] = r[1];
                bh[nfb + 1][0] = r[2]; bh[nfb + 1][1] = r[3];
                addr = pBl + ((nfb + bNf) * 8 + bRow) * PADB + kc0 + bKhalf * 2;
                ldm_x4(r, addr);
                bl[nfb][0] = r[0]; bl[nfb][1] = r[1];
                bl[nfb + 1][0] = r[2]; bl[nfb + 1][1] = r[3];
            }
#pragma unroll
            for (int mf = 0; mf < 4; mf++) {
                uint32_t ah[4], al[4];
                ldm_x4(ah, pAh + (mf * 16 + aRow) * PADB + kc0 + aKhalf * 2);
                ldm_x4(al, pAl + (mf * 16 + aRow) * PADB + kc0 + aKhalf * 2);
#pragma unroll
                for (int nf = 0; nf < 4; nf++) {
                    mma16816(acc[mf][nf], ah, bh[nf]);
                    mma16816(acc[mf][nf], ah, bl[nf]);
                    mma16816(acc[mf][nf], al, bh[nf]);
                }
            }
        }
    };

    load_chunk(0, 0);
    CP_COMMIT();
    for (int c = 0; c < nch; c++) {
        if (c + 1 < nch) {
            load_chunk(c + 1, (c + 1) & 1);
            CP_COMMIT();
            CP_WAIT1();
        } else {
            CP_WAIT0();
        }
        __syncthreads();
        compute_chunk(c & 1);
        __syncthreads();
    }

    // ---- epilogue ----
    if (OUTF) {
#pragma unroll
        for (int mf = 0; mf < 4; mf++) {
#pragma unroll
            for (int nf = 0; nf < 4; nf++) {
                const int mr0 = m0 + wm * 64 + mf * 16 + g;
                const int mr1 = mr0 + 8;
                const int n0  = wn * 32 + nf * 8 + 2 * t;
                const float* cc = acc[mf][nf];
                if (mr0 < A.Mvalid)
                    *(float2*)(A.Cf + z * A.sC + (long)mr0 * 128 + n0) =
                        make_float2(cc[0], cc[1]);
                if (mr1 < A.Mvalid)
                    *(float2*)(A.Cf + z * A.sC + (long)mr1 * 128 + n0) =
                        make_float2(cc[2], cc[3]);
            }
        }
    }

    if (OUTT) {
        // stage C into smem as [n][m_local], stride 132 (conflict-free scatter)
        float* ts = (float*)sm;
#pragma unroll
        for (int mf = 0; mf < 4; mf++) {
#pragma unroll
            for (int nf = 0; nf < 4; nf++) {
                const int ml0 = wm * 64 + mf * 16 + g;
                const int n0  = wn * 32 + nf * 8 + 2 * t;
                const float* cc = acc[mf][nf];
                ts[(n0    ) * 132 + ml0    ] = cc[0];
                ts[(n0 + 1) * 132 + ml0    ] = cc[1];
                ts[(n0    ) * 132 + ml0 + 8] = cc[2];
                ts[(n0 + 1) * 132 + ml0 + 8] = cc[3];
            }
        }
        __syncthreads();
        // coalesced store: thread -> (n, 64-row half). RB % 64 == 0 and
        // Mvalid % 64 == 0 for all call sites, so halves never straddle.
        const int n  = tid >> 1;
        const int mh = (tid & 1) * 64;
        if (m0 + mh < A.Mvalid) {
            const long bb  = (m0 + mh) / A.RB;
            const int  mlb = (m0 + mh) % A.RB;
            bf16* oh = A.CThi + z * A.sCT + bb * (128L * A.RB) + (long)n * A.RB + mlb;
            bf16* ol = A.CTlo + z * A.sCT + bb * (128L * A.RB) + (long)n * A.RB + mlb;
#pragma unroll
            for (int jj = 0; jj < 8; jj++) {
                float4 v0 = *(const float4*)&ts[n * 132 + mh + jj * 8];
                float4 v1 = *(const float4*)&ts[n * 132 + mh + jj * 8 + 4];
                __align__(16) bf16 hb[8], lb[8];
                split2(v0.x, hb[0], lb[0]); split2(v0.y, hb[1], lb[1]);
                split2(v0.z, hb[2], lb[2]); split2(v0.w, hb[3], lb[3]);
                split2(v1.x, hb[4], lb[4]); split2(v1.y, hb[5], lb[5]);
                split2(v1.z, hb[6], lb[6]); split2(v1.w, hb[7], lb[7]);
                *(uint4*)(oh + jj * 8) = *(const uint4*)hb;
                *(uint4*)(ol + jj * 8) = *(const uint4*)lb;
            }
        }
    }
}

// ===========================================================================
// Elementwise tail
// ===========================================================================
__global__ void score_kernel(const float* __restrict__ U,
                             const float* __restrict__ Vc,
                             const float* __restrict__ wh,
                             float* __restrict__ s, int total)
{
    int gw   = (blockIdx.x * blockDim.x + threadIdx.x) >> 5;
    int lane = threadIdx.x & 31;
    if (gw >= total) return;
    const float* u = U  + (long)gw * 128;
    const float* v = Vc + (long)gw * 128;
    float acc = 0.f;
#pragma unroll
    for (int k = 0; k < 4; k++) {
        int idx = lane + 32 * k;
        acc += tanhf(u[idx] + v[idx]) * wh[idx];
    }
#pragma unroll
    for (int o = 16; o > 0; o >>= 1)
        acc += __shfl_xor_sync(0xffffffffu, acc, o);
    if (lane == 0) s[gw] = acc;
}

__global__ void softmax_kernel(float* __restrict__ s, int L)
{
    float* row = s + (long)blockIdx.x * L;
    __shared__ float red[32];
    __shared__ float bval;
    const int tid  = threadIdx.x;
    const int lane = tid & 31;
    const int wid  = tid >> 5;
    const int nw   = blockDim.x >> 5;

    float m = -1e30f;
    for (int i = tid; i < L; i += blockDim.x) m = fmaxf(m, row[i]);
#pragma unroll
    for (int o = 16; o > 0; o >>= 1) m = fmaxf(m, __shfl_xor_sync(0xffffffffu, m, o));
    if (lane == 0) red[wid] = m;
    __syncthreads();
    if (tid == 0) {
        float mm = red[0];
        for (int w = 1; w < nw; w++) mm = fmaxf(mm, red[w]);
        bval = mm;
    }
    __syncthreads();
    m = bval;
    __syncthreads();

    float sum = 0.f;
    for (int i = tid; i < L; i += blockDim.x) {
        float e = expf(row[i] - m);
        row[i] = e;
        sum += e;
    }
#pragma unroll
    for (int o = 16; o > 0; o >>= 1) sum += __shfl_xor_sync(0xffffffffu, sum, o);
    if (lane == 0) red[wid] = sum;
    __syncthreads();
    if (tid == 0) {
        float ss = 0.f;
        for (int w = 0; w < nw; w++) ss += red[w];
        bval = ss;
    }
    __syncthreads();
    float inv = 1.f / bval;
    for (int i = tid; i < L; i += blockDim.x) row[i] *= inv;
}

__global__ void __launch_bounds__(768) context_kernel(
    const float* __restrict__ T, const float* __restrict__ I,
    const float* __restrict__ aq, const float* __restrict__ av,
    float* __restrict__ ctx)
{
    __shared__ float sq[cfg::LT];
    __shared__ float sv[cfg::LV];
    const int b = blockIdx.x;
    const int d = threadIdx.x;
    for (int i = d; i < cfg::LT; i += 768) sq[i] = aq[(long)b * cfg::LT + i];
    if (d < cfg::LV) sv[d] = av[(long)b * cfg::LV + d];
    __syncthreads();

    const float* Ib = I + (long)b * cfg::LV * cfg::E + d;
    const float* Tb = T + (long)b * cfg::LT * cfg::E + d;
    float acc = 0.f;
#pragma unroll 4
    for (int y = 0; y < cfg::LV; y++) acc += sv[y] * Ib[(long)y * cfg::E];
#pragma unroll 4
    for (int x = 0; x < cfg::LT; x++) acc += sq[x] * Tb[(long)x * cfg::E];
    ctx[(long)b * cfg::E + d] = acc;
}

__global__ void __launch_bounds__(768) out_kernel(
    const float* __restrict__ ctx, const float* __restrict__ ws,
    float* __restrict__ out)
{
    __shared__ float sc[cfg::E];
    const int b = blockIdx.x;
    const int e = threadIdx.x;
    sc[e] = ctx[(long)b * cfg::E + e];
    __syncthreads();
    float acc = 0.f;
#pragma unroll 8
    for (int d = 0; d < cfg::E; d++)
        acc += sc[d] * ws[(long)d * cfg::E + e];
    out[(long)b * cfg::E + e] = tanhf(acc);
}

// ===========================================================================
// launch
// ===========================================================================
extern "C" void kernel_launch(void* const* d_in, const int* in_sizes, int n_in,
                              void* d_out, int out_size)
{
    using namespace cfg;
    const float* T   = (const float*)d_in[0];
    const float* I   = (const float*)d_in[1];
    const float* wb  = (const float*)d_in[3];
    const float* wv  = (const float*)d_in[4];
    const float* wq  = (const float*)d_in[5];
    const float* whv = (const float*)d_in[6];
    const float* whq = (const float*)d_in[7];
    const float* ws  = (const float*)d_in[8];
    float* out = (float*)d_out;

    bf16 *Thi, *Tlo, *TThi, *TTlo, *Ihi, *Ilo, *IThi, *ITlo;
    bf16 *wbhi, *wblo, *wbThi, *wbTlo, *wqThi, *wqTlo, *wvThi, *wvTlo;
    bf16 *wqqThi, *wqqTlo, *wvvThi, *wvvTlo;
    bf16 *A1Thi, *A1Tlo, *M1Thi, *M1Tlo, *A2Thi, *A2Tlo, *HThi, *HTlo;
    float *wqq, *wvv, *wqqc, *wvvc, *sv, *sq, *ctx;

    cudaGetSymbolAddress((void**)&Thi, g_Thi);   cudaGetSymbolAddress((void**)&Tlo, g_Tlo);
    cudaGetSymbolAddress((void**)&TThi, g_TThi); cudaGetSymbolAddress((void**)&TTlo, g_TTlo);
    cudaGetSymbolAddress((void**)&Ihi, g_Ihi);   cudaGetSymbolAddress((void**)&Ilo, g_Ilo);
    cudaGetSymbolAddress((void**)&IThi, g_IThi); cudaGetSymbolAddress((void**)&ITlo, g_ITlo);
    cudaGetSymbolAddress((void**)&wbhi, g_wbhi); cudaGetSymbolAddress((void**)&wblo, g_wblo);
    cudaGetSymbolAddress((void**)&wbThi, g_wbThi); cudaGetSymbolAddress((void**)&wbTlo, g_wbTlo);
    cudaGetSymbolAddress((void**)&wqThi, g_wqThi); cudaGetSymbolAddress((void**)&wqTlo, g_wqTlo);
    cudaGetSymbolAddress((void**)&wvThi, g_wvThi); cudaGetSymbolAddress((void**)&wvTlo, g_wvTlo);
    cudaGetSymbolAddress((void**)&wqqThi, g_wqqThi); cudaGetSymbolAddress((void**)&wqqTlo, g_wqqTlo);
    cudaGetSymbolAddress((void**)&wvvThi, g_wvvThi); cudaGetSymbolAddress((void**)&wvvTlo, g_wvvTlo);
    cudaGetSymbolAddress((void**)&A1Thi, g_A1Thi); cudaGetSymbolAddress((void**)&A1Tlo, g_A1Tlo);
    cudaGetSymbolAddress((void**)&M1Thi, g_M1Thi); cudaGetSymbolAddress((void**)&M1Tlo, g_M1Tlo);
    cudaGetSymbolAddress((void**)&A2Thi, g_A2Thi); cudaGetSymbolAddress((void**)&A2Tlo, g_A2Tlo);
    cudaGetSymbolAddress((void**)&HThi, g_HThi);   cudaGetSymbolAddress((void**)&HTlo, g_HTlo);
    cudaGetSymbolAddress((void**)&wqq, g_wqq);   cudaGetSymbolAddress((void**)&wvv, g_wvv);
    cudaGetSymbolAddress((void**)&wqqc, g_wqqc); cudaGetSymbolAddress((void**)&wvvc, g_wvvc);
    cudaGetSymbolAddress((void**)&sv, g_sv);     cudaGetSymbolAddress((void**)&sq, g_sq);
    cudaGetSymbolAddress((void**)&ctx, g_ctx);

    cudaFuncSetAttribute(mma_gemm<true, true>,
        cudaFuncAttributeMaxDynamicSharedMemorySize, SMEM_MMA_BYTES);
    cudaFuncSetAttribute(mma_gemm<false, true>,
        cudaFuncAttributeMaxDynamicSharedMemorySize, SMEM_MMA_BYTES);
    cudaFuncSetAttribute(mma_gemm<true, false>,
        cudaFuncAttributeMaxDynamicSharedMemorySize, SMEM_MMA_BYTES);

    const dim3 cblk(32, 8);

    // --- conversions ---
    conv_split<<<dim3(E / 32, LT / 32, Bn), cblk>>>(
        T, (long)LT * E, Thi, Tlo, (long)LT * E, TThi, TTlo, (long)E * LT, LT, E);
    conv_split<<<dim3(E / 32, LV / 32, Bn), cblk>>>(
        I, (long)LV * E, Ihi, Ilo, (long)LV * E, IThi, ITlo, (long)E * LV, LV, E);
    conv_split<<<dim3(E / 32, E / 32, 1), cblk>>>(
        wb, 0, wbhi, wblo, 0, wbThi, wbTlo, 0, E, E);
    conv_split<<<dim3(Kd / 32, E / 32, 1), cblk>>>(
        wq, 0, nullptr, nullptr, 0, wqThi, wqTlo, 0, E, Kd);
    conv_split<<<dim3(Kd / 32, E / 32, 1), cblk>>>(
        wv, 0, nullptr, nullptr, 0, wvThi, wvTlo, 0, E, Kd);

    // --- 4 merged GEMM launches ---
    // [1+2]: wqq = T@w_q (flat M=65536) | wvv = I@w_v (flat M=36864)
    {
        GArgs a0{Thi, Tlo, wqThi, wqTlo, 0, 0, 0, 0,
                 wqq, wqqThi, wqqTlo, E, Bn * LT, LT};
        GArgs a1{Ihi, Ilo, wvThi, wvTlo, 0, 0, 0, 0,
                 wvv, wvvThi, wvvTlo, E, Bn * LV, LV};
        mma_gemm<true, true><<<dim3(512 + 288, 1, 1), 256, SMEM_MMA_BYTES>>>(
            a0, a1, 512);
    }
    // [3+6]: A1 = T^T@wqq (K=1024) | A2 = I^T@wvv (K=576), per-batch
    {
        GArgs a0{TThi, TTlo, wqqThi, wqqTlo,
                 (long)E * LT, (long)Kd * LT, 0, (long)Kd * E,
                 nullptr, A1Thi, A1Tlo, LT, E, E};
        GArgs a1{IThi, ITlo, wvvThi, wvvTlo,
                 (long)E * LV, (long)Kd * LV, 0, (long)Kd * E,
                 nullptr, A2Thi, A2Tlo, LV, E, E};
        mma_gemm<false, true><<<dim3(12, 1, Bn), 256, SMEM_MMA_BYTES>>>(
            a0, a1, 6);
    }
    // [4+7]: M1 = w_b^T@A1 | H = w_b@A2, per-batch (K=768)
    {
        GArgs a0{wbThi, wbTlo, A1Thi, A1Tlo,
                 0, (long)Kd * E, 0, (long)Kd * E,
                 nullptr, M1Thi, M1Tlo, E, E, E};
        GArgs a1{wbhi, wblo, A2Thi, A2Tlo,
                 0, (long)Kd * E, 0, (long)Kd * E,
                 nullptr, HThi, HTlo, E, E, E};
        mma_gemm<false, true><<<dim3(12, 1, Bn), 256, SMEM_MMA_BYTES>>>(
            a0, a1, 6);
    }
    // [5+8]: wqqc = I@M1 (M=576, masked) | wvvc = T@H (M=1024), per-batch
    {
        GArgs a0{Ihi, Ilo, M1Thi, M1Tlo,
                 (long)LV * E, (long)Kd * E, (long)LV * Kd, 0,
                 wqqc, nullptr, nullptr, E, LV, LV};
        GArgs a1{Thi, Tlo, HThi, HTlo,
                 (long)LT * E, (long)Kd * E, (long)LT * Kd, 0,
                 wvvc, nullptr, nullptr, E, LT, LT};
        mma_gemm<true, false><<<dim3(5 + 8, 1, Bn), 256, SMEM_MMA_BYTES>>>(
            a0, a1, 5);
    }

    // --- scores / softmax / context / output ---
    {
        int total_v = Bn * LV;
        int total_q = Bn * LT;
        score_kernel<<<(total_v * 32 + 255) / 256, 256>>>(wvv, wqqc, whv, sv, total_v);
        score_kernel<<<(total_q * 32 + 255) / 256, 256>>>(wqq, wvvc, whq, sq, total_q);
    }
    softmax_kernel<<<Bn, 256>>>(sv, LV);
    softmax_kernel<<<Bn, 256>>>(sq, LT);
    context_kernel<<<Bn, 768>>>(T, I, sq, sv, ctx);
    out_kernel<<<Bn, 768>>>(ctx, ws, out);
}

// round 7
// speedup vs baseline: 2.0433x; 1.0641x over previous
#include <cuda_runtime.h>
#include <cuda_bf16.h>
#include <math.h>
#include <stdint.h>

// Problem constants: B=64, LT=1024, LV=576, E=768, K=128
namespace cfg {
constexpr int Bn = 64;
constexpr int LT = 1024;
constexpr int LV = 576;
constexpr int E  = 768;
constexpr int Kd = 128;
}
using bf16 = __nv_bfloat16;

__device__ __forceinline__ void split2(float v, bf16& h, bf16& l) {
    h = __float2bfloat16(v);
    l = __float2bfloat16(v - __bfloat162float(h));
}

__device__ __forceinline__ void mma16816(float* d, const uint32_t* a, const uint32_t* b) {
    asm volatile(
        "mma.sync.aligned.m16n8k16.row.col.f32.bf16.bf16.f32 "
        "{%0,%1,%2,%3}, {%4,%5,%6,%7}, {%8,%9}, {%0,%1,%2,%3};"
        : "+f"(d[0]), "+f"(d[1]), "+f"(d[2]), "+f"(d[3])
        : "r"(a[0]), "r"(a[1]), "r"(a[2]), "r"(a[3]), "r"(b[0]), "r"(b[1]));
}

__device__ __forceinline__ void ldm_x4(uint32_t* r, uint32_t saddr) {
    asm volatile("ldmatrix.sync.aligned.m8n8.x4.shared.b16 {%0,%1,%2,%3}, [%4];"
        : "=r"(r[0]), "=r"(r[1]), "=r"(r[2]), "=r"(r[3]) : "r"(saddr));
}

__device__ __forceinline__ uint32_t smem_u32(const void* p) {
    uint32_t a;
    asm("{ .reg .u64 t; cvta.to.shared.u64 t, %1; cvt.u32.u64 %0, t; }"
        : "=r"(a) : "l"(p));
    return a;
}

#define CP_ASYNC16(s, g) \
    asm volatile("cp.async.cg.shared.global [%0], [%1], 16;" :: "r"(s), "l"(g))
#define CP_COMMIT() asm volatile("cp.async.commit_group;")
#define CP_WAIT1()  asm volatile("cp.async.wait_group 1;")
#define CP_WAIT0()  asm volatile("cp.async.wait_group 0;")

// 64B-row XOR swizzle: 16B-group of row r is (4r + (r&3) + k) mod 8 -> all
// 8 rows of an ldmatrix read hit distinct 16B groups (conflict-free).
#define SWZ(row, kb) ((uint32_t)((row) * 64 + ((kb) ^ (((row) & 3) << 4))))

// ===========================================================================
// Scratch (device globals)
// ===========================================================================
#define DEV_BF16(name, n) __device__ __align__(256) bf16 name[n]
DEV_BF16(g_Thi,  64 * 1024 * 768);
DEV_BF16(g_Tlo,  64 * 1024 * 768);
DEV_BF16(g_TThi, 64 * 768 * 1024);
DEV_BF16(g_TTlo, 64 * 768 * 1024);
DEV_BF16(g_Ihi,  64 * 576 * 768 + 64 * 768);   // +pad: GEMM5 reads 64 extra rows
DEV_BF16(g_Ilo,  64 * 576 * 768 + 64 * 768);
DEV_BF16(g_IThi, 64 * 768 * 576);
DEV_BF16(g_ITlo, 64 * 768 * 576);
DEV_BF16(g_wbhi,  768 * 768);
DEV_BF16(g_wblo,  768 * 768);
DEV_BF16(g_wbThi, 768 * 768);
DEV_BF16(g_wbTlo, 768 * 768);
DEV_BF16(g_wqThi, 128 * 768);
DEV_BF16(g_wqTlo, 128 * 768);
DEV_BF16(g_wvThi, 128 * 768);
DEV_BF16(g_wvTlo, 128 * 768);
DEV_BF16(g_wqqThi, 64 * 128 * 1024);
DEV_BF16(g_wqqTlo, 64 * 128 * 1024);
DEV_BF16(g_wvvThi, 64 * 128 * 576);
DEV_BF16(g_wvvTlo, 64 * 128 * 576);
DEV_BF16(g_A1Thi, 64 * 128 * 768);
DEV_BF16(g_A1Tlo, 64 * 128 * 768);
DEV_BF16(g_M1Thi, 64 * 128 * 768);
DEV_BF16(g_M1Tlo, 64 * 128 * 768);
DEV_BF16(g_A2Thi, 64 * 128 * 768);
DEV_BF16(g_A2Tlo, 64 * 128 * 768);
DEV_BF16(g_HThi,  64 * 128 * 768);
DEV_BF16(g_HTlo,  64 * 128 * 768);

__device__ float g_wqq [cfg::Bn * cfg::LT * cfg::Kd];
__device__ float g_wvv [cfg::Bn * cfg::LV * cfg::Kd];
__device__ float g_wqqc[cfg::Bn * cfg::LV * cfg::Kd];
__device__ float g_wvvc[cfg::Bn * cfg::LT * cfg::Kd];
__device__ float g_sv  [cfg::Bn * cfg::LV];
__device__ float g_sq  [cfg::Bn * cfg::LT];
__device__ float g_ctx [cfg::Bn * cfg::E];

// ===========================================================================
// Conversion: fp32 [z][R,C] -> bf16 hi/lo [z][R,C] and/or transposed [z][C,R]
// ===========================================================================
__global__ void conv_split(const float* __restrict__ X, long sX,
                           bf16* hi, bf16* lo, long sHL,
                           bf16* hiT, bf16* loT, long sT,
                           int R, int C)
{
    __shared__ float tile[32][33];
    const float* Xb = X + (long)blockIdx.z * sX;
    const int c0 = blockIdx.x * 32, r0 = blockIdx.y * 32;
    const int tx = threadIdx.x, ty = threadIdx.y;
#pragma unroll
    for (int j = 0; j < 4; j++) {
        int r = r0 + ty + j * 8;
        float v = Xb[(long)r * C + c0 + tx];
        tile[ty + j * 8][tx] = v;
        if (hi) {
            bf16 h, l; split2(v, h, l);
            long o = (long)blockIdx.z * sHL + (long)r * C + c0 + tx;
            hi[o] = h; lo[o] = l;
        }
    }
    __syncthreads();
    if (hiT) {
#pragma unroll
        for (int j = 0; j < 4; j++) {
            int cc = c0 + ty + j * 8;
            int rr = r0 + tx;
            float v = tile[tx][ty + j * 8];
            bf16 h, l; split2(v, h, l);
            long o = (long)blockIdx.z * sT + (long)cc * R + rr;
            hiT[o] = h; loT[o] = l;
        }
    }
}

// ===========================================================================
// Merged-pair HMMA batched GEMM.  C[M,128] = A[M,K] @ B[K,128] (bf16x3 split)
// 3-stage cp.async pipeline, 64B-row swizzled smem, one sync per K-chunk.
// ===========================================================================
constexpr int MATB   = 128 * 64;           // 8192 B per matrix tile
constexpr int STAGEB = 4 * MATB;           // 32768 B (Ah, Al, Bh, Bl)
static constexpr int SMEM_MMA_BYTES = 3 * STAGEB;   // 98304 B

struct GArgs {
    const bf16 *Ahi, *Alo, *Bhi, *Blo;
    long sA, sB, sC, sCT;
    float* Cf;
    bf16 *CThi, *CTlo;
    int Ktot, Mvalid, RB;
};

template <bool OUTF, bool OUTT>
__global__ void __launch_bounds__(256, 2) mma_gemm(GArgs a0, GArgs a1, int splitX)
{
    extern __shared__ __align__(16) bf16 sm[];
    const uint32_t smb = smem_u32(sm);

    const GArgs& A = (blockIdx.x < (unsigned)splitX) ? a0 : a1;
    const int bx = (blockIdx.x < (unsigned)splitX) ? blockIdx.x
                                                   : blockIdx.x - splitX;

    const int tid  = threadIdx.x;
    const int lane = tid & 31;
    const int wid  = tid >> 5;
    const int wm   = wid & 1;
    const int wn   = wid >> 1;
    const int g    = lane >> 2;
    const int t    = lane & 3;

    const long z  = blockIdx.z;
    const int  m0 = bx * 128;
    const int  Ktot = A.Ktot;

    const bf16* Ah = A.Ahi + z * A.sA + (long)m0 * Ktot;
    const bf16* Al = A.Alo + z * A.sA + (long)m0 * Ktot;
    const bf16* Bh = A.Bhi + z * A.sB;
    const bf16* Bl = A.Blo + z * A.sB;

    float acc[4][4][4];
#pragma unroll
    for (int i = 0; i < 4; i++)
#pragma unroll
        for (int j = 0; j < 4; j++)
#pragma unroll
            for (int q = 0; q < 4; q++) acc[i][j][q] = 0.f;

    const int nch = Ktot >> 5;

    // per-thread cp.async coordinates: 2 x 16B units per matrix tile
    const int lrow0 = (tid * 2)     >> 2, lc0 = ((tid * 2)     & 3) * 16;
    const int lrow1 = (tid * 2 + 1) >> 2, lc1 = ((tid * 2 + 1) & 3) * 16;

    auto load_chunk = [&](int c, int stage) {
        const int k0 = c << 5;
        const bf16* srcs[4] = {Ah, Al, Bh, Bl};
        const uint32_t sb = smb + stage * STAGEB;
#pragma unroll
        for (int mt = 0; mt < 4; mt++) {
            const bf16* src = srcs[mt];
            const uint32_t dst = sb + mt * MATB;
            CP_ASYNC16(dst + SWZ(lrow0, lc0),
                       src + (long)lrow0 * Ktot + k0 + lc0 / 2);
            CP_ASYNC16(dst + SWZ(lrow1, lc1),
                       src + (long)lrow1 * Ktot + k0 + lc1 / 2);
        }
    };

    // ldmatrix lane-derived coordinates
    const int aRow   = (lane & 7) + ((lane >> 3) & 1) * 8;  // row within 16
    const int aKB    = (lane >> 4) * 16;                    // 0 or 16 bytes
    const int bQ     = lane >> 3;
    const int bNf    = bQ >> 1;
    const int bKB    = (bQ & 1) * 16;
    const int bRow   = lane & 7;

    auto compute_chunk = [&](int stage) {
        const uint32_t sb  = smb + stage * STAGEB;
        const uint32_t tAh = sb;
        const uint32_t tAl = sb + MATB;
        const uint32_t tBh = sb + 2 * MATB;
        const uint32_t tBl = sb + 3 * MATB;
#pragma unroll
        for (int ks = 0; ks < 2; ks++) {
            const int kc0 = ks * 32;   // bytes
            uint32_t bh[4][2], bl[4][2];
#pragma unroll
            for (int nfb = 0; nfb < 4; nfb += 2) {
                const int rowB = wn * 32 + (nfb + bNf) * 8 + bRow;
                const int kbB  = kc0 + bKB;
                uint32_t r[4];
                ldm_x4(r, tBh + SWZ(rowB, kbB));
                bh[nfb][0] = r[0]; bh[nfb][1] = r[1];
                bh[nfb + 1][0] = r[2]; bh[nfb + 1][1] = r[3];
                ldm_x4(r, tBl + SWZ(rowB, kbB));
                bl[nfb][0] = r[0]; bl[nfb][1] = r[1];
                bl[nfb + 1][0] = r[2]; bl[nfb + 1][1] = r[3];
            }
#pragma unroll
            for (int mf = 0; mf < 4; mf++) {
                const int rowA = wm * 64 + mf * 16 + aRow;
                const int kbA  = kc0 + aKB;
                uint32_t ah[4], al[4];
                ldm_x4(ah, tAh + SWZ(rowA, kbA));
                ldm_x4(al, tAl + SWZ(rowA, kbA));
#pragma unroll
                for (int nf = 0; nf < 4; nf++) {
                    mma16816(acc[mf][nf], ah, bh[nf]);
                    mma16816(acc[mf][nf], ah, bl[nf]);
                    mma16816(acc[mf][nf], al, bh[nf]);
                }
            }
        }
    };

    // 3-stage pipeline, one barrier per chunk
    load_chunk(0, 0);
    CP_COMMIT();
    if (nch > 1) { load_chunk(1, 1); CP_COMMIT(); }
    for (int c = 0; c < nch; c++) {
        if (c + 1 < nch) CP_WAIT1(); else CP_WAIT0();
        __syncthreads();
        compute_chunk(c % 3);
        if (c + 2 < nch) {
            // stage (c+2)%3 == (c-1)%3 was last read in iteration c-1; the
            // barrier above already separates those reads from this write.
            load_chunk(c + 2, (c + 2) % 3);
            CP_COMMIT();
        }
    }

    // ---- epilogue ----
    if (OUTF) {
#pragma unroll
        for (int mf = 0; mf < 4; mf++) {
#pragma unroll
            for (int nf = 0; nf < 4; nf++) {
                const int mr0 = m0 + wm * 64 + mf * 16 + g;
                const int mr1 = mr0 + 8;
                const int n0  = wn * 32 + nf * 8 + 2 * t;
                const float* cc = acc[mf][nf];
                if (mr0 < A.Mvalid)
                    *(float2*)(A.Cf + z * A.sC + (long)mr0 * 128 + n0) =
                        make_float2(cc[0], cc[1]);
                if (mr1 < A.Mvalid)
                    *(float2*)(A.Cf + z * A.sC + (long)mr1 * 128 + n0) =
                        make_float2(cc[2], cc[3]);
            }
        }
    }

    if (OUTT) {
        __syncthreads();   // all warps done reading smem stages
        float* ts = (float*)sm;
#pragma unroll
        for (int mf = 0; mf < 4; mf++) {
#pragma unroll
            for (int nf = 0; nf < 4; nf++) {
                const int ml0 = wm * 64 + mf * 16 + g;
                const int n0  = wn * 32 + nf * 8 + 2 * t;
                const float* cc = acc[mf][nf];
                ts[(n0    ) * 132 + ml0    ] = cc[0];
                ts[(n0 + 1) * 132 + ml0    ] = cc[1];
                ts[(n0    ) * 132 + ml0 + 8] = cc[2];
                ts[(n0 + 1) * 132 + ml0 + 8] = cc[3];
            }
        }
        __syncthreads();
        const int n  = tid >> 1;
        const int mh = (tid & 1) * 64;
        if (m0 + mh < A.Mvalid) {
            const long bb  = (m0 + mh) / A.RB;
            const int  mlb = (m0 + mh) % A.RB;
            bf16* oh = A.CThi + z * A.sCT + bb * (128L * A.RB) + (long)n * A.RB + mlb;
            bf16* ol = A.CTlo + z * A.sCT + bb * (128L * A.RB) + (long)n * A.RB + mlb;
#pragma unroll
            for (int jj = 0; jj < 8; jj++) {
                float4 v0 = *(const float4*)&ts[n * 132 + mh + jj * 8];
                float4 v1 = *(const float4*)&ts[n * 132 + mh + jj * 8 + 4];
                __align__(16) bf16 hb[8], lb[8];
                split2(v0.x, hb[0], lb[0]); split2(v0.y, hb[1], lb[1]);
                split2(v0.z, hb[2], lb[2]); split2(v0.w, hb[3], lb[3]);
                split2(v1.x, hb[4], lb[4]); split2(v1.y, hb[5], lb[5]);
                split2(v1.z, hb[6], lb[6]); split2(v1.w, hb[7], lb[7]);
                *(uint4*)(oh + jj * 8) = *(const uint4*)hb;
                *(uint4*)(ol + jj * 8) = *(const uint4*)lb;
            }
        }
    }
}

// ===========================================================================
// Elementwise tail
// ===========================================================================
__global__ void score_kernel(const float* __restrict__ U,
                             const float* __restrict__ Vc,
                             const float* __restrict__ wh,
                             float* __restrict__ s, int total)
{
    int gw   = (blockIdx.x * blockDim.x + threadIdx.x) >> 5;
    int lane = threadIdx.x & 31;
    if (gw >= total) return;
    const float* u = U  + (long)gw * 128;
    const float* v = Vc + (long)gw * 128;
    float acc = 0.f;
#pragma unroll
    for (int k = 0; k < 4; k++) {
        int idx = lane + 32 * k;
        acc += tanhf(u[idx] + v[idx]) * wh[idx];
    }
#pragma unroll
    for (int o = 16; o > 0; o >>= 1)
        acc += __shfl_xor_sync(0xffffffffu, acc, o);
    if (lane == 0) s[gw] = acc;
}

__global__ void softmax_kernel(float* __restrict__ s, int L)
{
    float* row = s + (long)blockIdx.x * L;
    __shared__ float red[32];
    __shared__ float bval;
    const int tid  = threadIdx.x;
    const int lane = tid & 31;
    const int wid  = tid >> 5;
    const int nw   = blockDim.x >> 5;

    float m = -1e30f;
    for (int i = tid; i < L; i += blockDim.x) m = fmaxf(m, row[i]);
#pragma unroll
    for (int o = 16; o > 0; o >>= 1) m = fmaxf(m, __shfl_xor_sync(0xffffffffu, m, o));
    if (lane == 0) red[wid] = m;
    __syncthreads();
    if (tid == 0) {
        float mm = red[0];
        for (int w = 1; w < nw; w++) mm = fmaxf(mm, red[w]);
        bval = mm;
    }
    __syncthreads();
    m = bval;
    __syncthreads();

    float sum = 0.f;
    for (int i = tid; i < L; i += blockDim.x) {
        float e = expf(row[i] - m);
        row[i] = e;
        sum += e;
    }
#pragma unroll
    for (int o = 16; o > 0; o >>= 1) sum += __shfl_xor_sync(0xffffffffu, sum, o);
    if (lane == 0) red[wid] = sum;
    __syncthreads();
    if (tid == 0) {
        float ss = 0.f;
        for (int w = 0; w < nw; w++) ss += red[w];
        bval = ss;
    }
    __syncthreads();
    float inv = 1.f / bval;
    for (int i = tid; i < L; i += blockDim.x) row[i] *= inv;
}

__global__ void __launch_bounds__(768) context_kernel(
    const float* __restrict__ T, const float* __restrict__ I,
    const float* __restrict__ aq, const float* __restrict__ av,
    float* __restrict__ ctx)
{
    __shared__ float sq[cfg::LT];
    __shared__ float sv[cfg::LV];
    const int b = blockIdx.x;
    const int d = threadIdx.x;
    for (int i = d; i < cfg::LT; i += 768) sq[i] = aq[(long)b * cfg::LT + i];
    if (d < cfg::LV) sv[d] = av[(long)b * cfg::LV + d];
    __syncthreads();

    const float* Ib = I + (long)b * cfg::LV * cfg::E + d;
    const float* Tb = T + (long)b * cfg::LT * cfg::E + d;
    float acc = 0.f;
#pragma unroll 4
    for (int y = 0; y < cfg::LV; y++) acc += sv[y] * Ib[(long)y * cfg::E];
#pragma unroll 4
    for (int x = 0; x < cfg::LT; x++) acc += sq[x] * Tb[(long)x * cfg::E];
    ctx[(long)b * cfg::E + d] = acc;
}

__global__ void __launch_bounds__(768) out_kernel(
    const float* __restrict__ ctx, const float* __restrict__ ws,
    float* __restrict__ out)
{
    __shared__ float sc[cfg::E];
    const int b = blockIdx.x;
    const int e = threadIdx.x;
    sc[e] = ctx[(long)b * cfg::E + e];
    __syncthreads();
    float acc = 0.f;
#pragma unroll 8
    for (int d = 0; d < cfg::E; d++)
        acc += sc[d] * ws[(long)d * cfg::E + e];
    out[(long)b * cfg::E + e] = tanhf(acc);
}

// ===========================================================================
// launch
// ===========================================================================
extern "C" void kernel_launch(void* const* d_in, const int* in_sizes, int n_in,
                              void* d_out, int out_size)
{
    using namespace cfg;
    const float* T   = (const float*)d_in[0];
    const float* I   = (const float*)d_in[1];
    const float* wb  = (const float*)d_in[3];
    const float* wv  = (const float*)d_in[4];
    const float* wq  = (const float*)d_in[5];
    const float* whv = (const float*)d_in[6];
    const float* whq = (const float*)d_in[7];
    const float* ws  = (const float*)d_in[8];
    float* out = (float*)d_out;

    bf16 *Thi, *Tlo, *TThi, *TTlo, *Ihi, *Ilo, *IThi, *ITlo;
    bf16 *wbhi, *wblo, *wbThi, *wbTlo, *wqThi, *wqTlo, *wvThi, *wvTlo;
    bf16 *wqqThi, *wqqTlo, *wvvThi, *wvvTlo;
    bf16 *A1Thi, *A1Tlo, *M1Thi, *M1Tlo, *A2Thi, *A2Tlo, *HThi, *HTlo;
    float *wqq, *wvv, *wqqc, *wvvc, *sv, *sq, *ctx;

    cudaGetSymbolAddress((void**)&Thi, g_Thi);   cudaGetSymbolAddress((void**)&Tlo, g_Tlo);
    cudaGetSymbolAddress((void**)&TThi, g_TThi); cudaGetSymbolAddress((void**)&TTlo, g_TTlo);
    cudaGetSymbolAddress((void**)&Ihi, g_Ihi);   cudaGetSymbolAddress((void**)&Ilo, g_Ilo);
    cudaGetSymbolAddress((void**)&IThi, g_IThi); cudaGetSymbolAddress((void**)&ITlo, g_ITlo);
    cudaGetSymbolAddress((void**)&wbhi, g_wbhi); cudaGetSymbolAddress((void**)&wblo, g_wblo);
    cudaGetSymbolAddress((void**)&wbThi, g_wbThi); cudaGetSymbolAddress((void**)&wbTlo, g_wbTlo);
    cudaGetSymbolAddress((void**)&wqThi, g_wqThi); cudaGetSymbolAddress((void**)&wqTlo, g_wqTlo);
    cudaGetSymbolAddress((void**)&wvThi, g_wvThi); cudaGetSymbolAddress((void**)&wvTlo, g_wvTlo);
    cudaGetSymbolAddress((void**)&wqqThi, g_wqqThi); cudaGetSymbolAddress((void**)&wqqTlo, g_wqqTlo);
    cudaGetSymbolAddress((void**)&wvvThi, g_wvvThi); cudaGetSymbolAddress((void**)&wvvTlo, g_wvvTlo);
    cudaGetSymbolAddress((void**)&A1Thi, g_A1Thi); cudaGetSymbolAddress((void**)&A1Tlo, g_A1Tlo);
    cudaGetSymbolAddress((void**)&M1Thi, g_M1Thi); cudaGetSymbolAddress((void**)&M1Tlo, g_M1Tlo);
    cudaGetSymbolAddress((void**)&A2Thi, g_A2Thi); cudaGetSymbolAddress((void**)&A2Tlo, g_A2Tlo);
    cudaGetSymbolAddress((void**)&HThi, g_HThi);   cudaGetSymbolAddress((void**)&HTlo, g_HTlo);
    cudaGetSymbolAddress((void**)&wqq, g_wqq);   cudaGetSymbolAddress((void**)&wvv, g_wvv);
    cudaGetSymbolAddress((void**)&wqqc, g_wqqc); cudaGetSymbolAddress((void**)&wvvc, g_wvvc);
    cudaGetSymbolAddress((void**)&sv, g_sv);     cudaGetSymbolAddress((void**)&sq, g_sq);
    cudaGetSymbolAddress((void**)&ctx, g_ctx);

    cudaFuncSetAttribute(mma_gemm<true, true>,
        cudaFuncAttributeMaxDynamicSharedMemorySize, SMEM_MMA_BYTES);
    cudaFuncSetAttribute(mma_gemm<false, true>,
        cudaFuncAttributeMaxDynamicSharedMemorySize, SMEM_MMA_BYTES);
    cudaFuncSetAttribute(mma_gemm<true, false>,
        cudaFuncAttributeMaxDynamicSharedMemorySize, SMEM_MMA_BYTES);

    const dim3 cblk(32, 8);

    // --- conversions ---
    conv_split<<<dim3(E / 32, LT / 32, Bn), cblk>>>(
        T, (long)LT * E, Thi, Tlo, (long)LT * E, TThi, TTlo, (long)E * LT, LT, E);
    conv_split<<<dim3(E / 32, LV / 32, Bn), cblk>>>(
        I, (long)LV * E, Ihi, Ilo, (long)LV * E, IThi, ITlo, (long)E * LV, LV, E);
    conv_split<<<dim3(E / 32, E / 32, 1), cblk>>>(
        wb, 0, wbhi, wblo, 0, wbThi, wbTlo, 0, E, E);
    conv_split<<<dim3(Kd / 32, E / 32, 1), cblk>>>(
        wq, 0, nullptr, nullptr, 0, wqThi, wqTlo, 0, E, Kd);
    conv_split<<<dim3(Kd / 32, E / 32, 1), cblk>>>(
        wv, 0, nullptr, nullptr, 0, wvThi, wvTlo, 0, E, Kd);

    // --- 4 merged GEMM launches ---
    {
        GArgs a0{Thi, Tlo, wqThi, wqTlo, 0, 0, 0, 0,
                 wqq, wqqThi, wqqTlo, E, Bn * LT, LT};
        GArgs a1{Ihi, Ilo, wvThi, wvTlo, 0, 0, 0, 0,
                 wvv, wvvThi, wvvTlo, E, Bn * LV, LV};
        mma_gemm<true, true><<<dim3(512 + 288, 1, 1), 256, SMEM_MMA_BYTES>>>(
            a0, a1, 512);
    }
    {
        GArgs a0{TThi, TTlo, wqqThi, wqqTlo,
                 (long)E * LT, (long)Kd * LT, 0, (long)Kd * E,
                 nullptr, A1Thi, A1Tlo, LT, E, E};
        GArgs a1{IThi, ITlo, wvvThi, wvvTlo,
                 (long)E * LV, (long)Kd * LV, 0, (long)Kd * E,
                 nullptr, A2Thi, A2Tlo, LV, E, E};
        mma_gemm<false, true><<<dim3(12, 1, Bn), 256, SMEM_MMA_BYTES>>>(
            a0, a1, 6);
    }
    {
        GArgs a0{wbThi, wbTlo, A1Thi, A1Tlo,
                 0, (long)Kd * E, 0, (long)Kd * E,
                 nullptr, M1Thi, M1Tlo, E, E, E};
        GArgs a1{wbhi, wblo, A2Thi, A2Tlo,
                 0, (long)Kd * E, 0, (long)Kd * E,
                 nullptr, HThi, HTlo, E, E, E};
        mma_gemm<false, true><<<dim3(12, 1, Bn), 256, SMEM_MMA_BYTES>>>(
            a0, a1, 6);
    }
    {
        GArgs a0{Ihi, Ilo, M1Thi, M1Tlo,
                 (long)LV * E, (long)Kd * E, (long)LV * Kd, 0,
                 wqqc, nullptr, nullptr, E, LV, LV};
        GArgs a1{Thi, Tlo, HThi, HTlo,
                 (long)LT * E, (long)Kd * E, (long)LT * Kd, 0,
                 wvvc, nullptr, nullptr, E, LT, LT};
        mma_gemm<true, false><<<dim3(5 + 8, 1, Bn), 256, SMEM_MMA_BYTES>>>(
            a0, a1, 5);
    }

    // --- scores / softmax / context / output ---
    {
        int total_v = Bn * LV;
        int total_q = Bn * LT;
        score_kernel<<<(total_v * 32 + 255) / 256, 256>>>(wvv, wqqc, whv, sv, total_v);
        score_kernel<<<(total_q * 32 + 255) / 256, 256>>>(wqq, wvvc, whq, sq, total_q);
    }
    softmax_kernel<<<Bn, 256>>>(sv, LV);
    softmax_kernel<<<Bn, 256>>>(sq, LT);
    context_kernel<<<Bn, 768>>>(T, I, sq, sv, ctx);
    out_kernel<<<Bn, 768>>>(ctx, ws, out);
}

// round 8
// speedup vs baseline: 2.2716x; 1.1117x over previous
#include <cuda_runtime.h>
#include <cuda_bf16.h>
#include <math.h>
#include <stdint.h>

// Problem constants: B=64, LT=1024, LV=576, E=768, K=128
namespace cfg {
constexpr int Bn = 64;
constexpr int LT = 1024;
constexpr int LV = 576;
constexpr int E  = 768;
constexpr int Kd = 128;
}
using bf16 = __nv_bfloat16;

__device__ __forceinline__ void split2(float v, bf16& h, bf16& l) {
    h = __float2bfloat16(v);
    l = __float2bfloat16(v - __bfloat162float(h));
}

__device__ __forceinline__ uint32_t pack_bf2(bf16 a, bf16 b) {
    union { bf16 h[2]; uint32_t u; } w;
    w.h[0] = a; w.h[1] = b;
    return w.u;
}

__device__ __forceinline__ void mma16816(float* d, const uint32_t* a, const uint32_t* b) {
    asm volatile(
        "mma.sync.aligned.m16n8k16.row.col.f32.bf16.bf16.f32 "
        "{%0,%1,%2,%3}, {%4,%5,%6,%7}, {%8,%9}, {%0,%1,%2,%3};"
        : "+f"(d[0]), "+f"(d[1]), "+f"(d[2]), "+f"(d[3])
        : "r"(a[0]), "r"(a[1]), "r"(a[2]), "r"(a[3]), "r"(b[0]), "r"(b[1]));
}

__device__ __forceinline__ void ldm_x4(uint32_t* r, uint32_t saddr) {
    asm volatile("ldmatrix.sync.aligned.m8n8.x4.shared.b16 {%0,%1,%2,%3}, [%4];"
        : "=r"(r[0]), "=r"(r[1]), "=r"(r[2]), "=r"(r[3]) : "r"(saddr));
}
__device__ __forceinline__ void ldm_x4t(uint32_t* r, uint32_t saddr) {
    asm volatile("ldmatrix.sync.aligned.m8n8.x4.trans.shared.b16 {%0,%1,%2,%3}, [%4];"
        : "=r"(r[0]), "=r"(r[1]), "=r"(r[2]), "=r"(r[3]) : "r"(saddr));
}

__device__ __forceinline__ uint32_t smem_u32(const void* p) {
    uint32_t a;
    asm("{ .reg .u64 t; cvta.to.shared.u64 t, %1; cvt.u32.u64 %0, t; }"
        : "=r"(a) : "l"(p));
    return a;
}

#define CP_ASYNC16(s, g) \
    asm volatile("cp.async.cg.shared.global [%0], [%1], 16;" :: "r"(s), "l"(g))
#define CP_COMMIT() asm volatile("cp.async.commit_group;")
#define CP_WAIT1()  asm volatile("cp.async.wait_group 1;")
#define CP_WAIT0()  asm volatile("cp.async.wait_group 0;")

// Swizzles (both verified conflict-free for their ldmatrix phases):
// 64B rows (normal-A tiles, 128 rows x 32 bf16)
#define SWZ64(row, kb)  ((uint32_t)((row) * 64  + ((kb) ^ (((row) & 3) << 4))))
// 256B rows (trans A/B tiles, 32 k-rows x 128 bf16)
#define SWZ256(row, kb) ((uint32_t)((row) * 256 + ((kb) ^ (((row) & 7) << 4))))

// ===========================================================================
// Scratch (device globals; zero-initialized)
// ===========================================================================
#define DEV_BF16(name, n) __device__ __align__(256) bf16 name[n]
DEV_BF16(g_Thi,  64 * 1024 * 768);
DEV_BF16(g_Tlo,  64 * 1024 * 768);
DEV_BF16(g_Ihi,  64 * 576 * 768 + 64 * 768);   // +pad: GEMM5 reads 64 extra rows
DEV_BF16(g_Ilo,  64 * 576 * 768 + 64 * 768);
DEV_BF16(g_wbhi,  768 * 768);
DEV_BF16(g_wblo,  768 * 768);
DEV_BF16(g_wqhi,  768 * 128);
DEV_BF16(g_wqlo,  768 * 128);
DEV_BF16(g_wvhi,  768 * 128);
DEV_BF16(g_wvlo,  768 * 128);
DEV_BF16(g_wqqhi, 64 * 1024 * 128);
DEV_BF16(g_wqqlo, 64 * 1024 * 128);
DEV_BF16(g_wvvhi, 64 * 576 * 128);
DEV_BF16(g_wvvlo, 64 * 576 * 128);
DEV_BF16(g_A1hi,  64 * 768 * 128);
DEV_BF16(g_A1lo,  64 * 768 * 128);
DEV_BF16(g_M1hi,  64 * 768 * 128);
DEV_BF16(g_M1lo,  64 * 768 * 128);
DEV_BF16(g_A2hi,  64 * 768 * 128);
DEV_BF16(g_A2lo,  64 * 768 * 128);
DEV_BF16(g_Hhi,   64 * 768 * 128);
DEV_BF16(g_Hlo,   64 * 768 * 128);

__device__ float g_wqq [cfg::Bn * cfg::LT * cfg::Kd];
__device__ float g_wvv [cfg::Bn * cfg::LV * cfg::Kd];
__device__ float g_sv  [cfg::Bn * cfg::LV];
__device__ float g_sq  [cfg::Bn * cfg::LT];
__device__ float g_ctx [cfg::Bn * cfg::E];

// ===========================================================================
// Flat conversion: fp32 -> bf16 hi/lo (no transposes needed anymore)
// ===========================================================================
__global__ void conv_flat(const float* __restrict__ X,
                          bf16* __restrict__ hi, bf16* __restrict__ lo, long n4)
{
    long idx = (long)blockIdx.x * blockDim.x + threadIdx.x;
    if (idx >= n4) return;
    float4 v = ((const float4*)X)[idx];
    union { bf16 h[4]; uint2 u; } H, L;
    split2(v.x, H.h[0], L.h[0]);
    split2(v.y, H.h[1], L.h[1]);
    split2(v.z, H.h[2], L.h[2]);
    split2(v.w, H.h[3], L.h[3]);
    ((uint2*)hi)[idx] = H.u;
    ((uint2*)lo)[idx] = L.u;
}

// ===========================================================================
// Merged-pair HMMA batched GEMM: C[M,128] = op(A)[M,K] @ B[K,128]
//   (fp32 via bf16x3 split; 3-stage cp.async; ldmatrix(.trans))
// A: natural [M,768] (transA=0) or [K,768]-stored A^T (transA=1), ld=768.
// B: ALWAYS natural [K,128] hi/lo, loaded via ldmatrix.trans.
// Outputs: OUTF fp32 [M,128]; OUTHL hi/lo bf16 [M,128];
//          OUTS fused score: s[m] = sum_n tanh(U[m,n]+C[m,n])*wh[n].
// ===========================================================================
constexpr int MATB   = 8192;               // bytes per matrix tile
constexpr int STAGEB = 4 * MATB;           // Ah, Al, Bh, Bl
static constexpr int SMEM_MMA_BYTES = 3 * STAGEB;   // 98304 B

struct GArgs {
    const bf16 *Ahi, *Alo, *Bhi, *Blo;
    long sA, sB, sC, sHL, sU, sS;
    float* Cf;
    bf16 *Chi, *Clo;
    const float *Uf, *wh;
    float* Sout;
    int Ktot, Mvalid, transA;
};

template <bool OUTF, bool OUTHL, bool OUTS>
__global__ void __launch_bounds__(256, 2) mma_gemm(GArgs a0, GArgs a1, int splitX)
{
    extern __shared__ __align__(16) bf16 sm[];
    __shared__ float s_wh[128];
    const uint32_t smb = smem_u32(sm);

    const GArgs& A = (blockIdx.x < (unsigned)splitX) ? a0 : a1;
    const int bx = (blockIdx.x < (unsigned)splitX) ? blockIdx.x
                                                   : blockIdx.x - splitX;

    const int tid  = threadIdx.x;
    const int lane = tid & 31;
    const int wid  = tid >> 5;
    const int wm   = wid & 1;
    const int wn   = wid >> 1;
    const int g    = lane >> 2;
    const int t    = lane & 3;

    const long z    = blockIdx.z;
    const int  m0   = bx * 128;
    const int  Ktot = A.Ktot;
    const bool trA  = (A.transA != 0);

    if (OUTS && tid < 128) s_wh[tid] = A.wh[tid];

    const bf16* Ah = A.Ahi + z * A.sA + (trA ? 0 : (long)m0 * 768);
    const bf16* Al = A.Alo + z * A.sA + (trA ? 0 : (long)m0 * 768);
    const bf16* Bh = A.Bhi + z * A.sB;
    const bf16* Bl = A.Blo + z * A.sB;

    float acc[4][4][4];
#pragma unroll
    for (int i = 0; i < 4; i++)
#pragma unroll
        for (int j = 0; j < 4; j++)
#pragma unroll
            for (int q = 0; q < 4; q++) acc[i][j][q] = 0.f;

    const int nch = Ktot >> 5;

    // cp.async per-thread coordinates
    const int nrow0 = (tid * 2)     >> 2, nc0 = ((tid * 2)     & 3) * 16; // normal-A
    const int nrow1 = (tid * 2 + 1) >> 2, nc1 = ((tid * 2 + 1) & 3) * 16;
    const int trow0 = (tid * 2)     >> 4, tc0 = ((tid * 2)     & 15) * 16; // trans tiles
    const int trow1 = (tid * 2 + 1) >> 4, tc1 = ((tid * 2 + 1) & 15) * 16;

    auto load_chunk = [&](int c, int stage) {
        const int k0 = c << 5;
        const uint32_t sb = smb + stage * STAGEB;
        // --- A tiles ---
        if (trA) {
            CP_ASYNC16(sb + SWZ256(trow0, tc0),
                       Ah + (long)(k0 + trow0) * 768 + m0 + tc0 / 2);
            CP_ASYNC16(sb + SWZ256(trow1, tc1),
                       Ah + (long)(k0 + trow1) * 768 + m0 + tc1 / 2);
            CP_ASYNC16(sb + MATB + SWZ256(trow0, tc0),
                       Al + (long)(k0 + trow0) * 768 + m0 + tc0 / 2);
            CP_ASYNC16(sb + MATB + SWZ256(trow1, tc1),
                       Al + (long)(k0 + trow1) * 768 + m0 + tc1 / 2);
        } else {
            CP_ASYNC16(sb + SWZ64(nrow0, nc0),
                       Ah + (long)nrow0 * 768 + k0 + nc0 / 2);
            CP_ASYNC16(sb + SWZ64(nrow1, nc1),
                       Ah + (long)nrow1 * 768 + k0 + nc1 / 2);
            CP_ASYNC16(sb + MATB + SWZ64(nrow0, nc0),
                       Al + (long)nrow0 * 768 + k0 + nc0 / 2);
            CP_ASYNC16(sb + MATB + SWZ64(nrow1, nc1),
                       Al + (long)nrow1 * 768 + k0 + nc1 / 2);
        }
        // --- B tiles (natural [K,128]) ---
        CP_ASYNC16(sb + 2 * MATB + SWZ256(trow0, tc0),
                   Bh + (long)(k0 + trow0) * 128 + tc0 / 2);
        CP_ASYNC16(sb + 2 * MATB + SWZ256(trow1, tc1),
                   Bh + (long)(k0 + trow1) * 128 + tc1 / 2);
        CP_ASYNC16(sb + 3 * MATB + SWZ256(trow0, tc0),
                   Bl + (long)(k0 + trow0) * 128 + tc0 / 2);
        CP_ASYNC16(sb + 3 * MATB + SWZ256(trow1, tc1),
                   Bl + (long)(k0 + trow1) * 128 + tc1 / 2);
    };

    // ldmatrix lane-derived coordinates
    const int tr_r = lane & 7, tr_q = lane >> 3;
    // B trans: matrices (k0-7,n0), (k8-15,n0), (k0-7,n+8), (k8-15,n+8)
    const int klB = (tr_q & 1) * 8 + tr_r;
    const int nbB = (tr_q >> 1) * 16;            // byte offset within row
    // A trans: matrices (m0,k0-7), (m+8,k0-7), (m0,k8-15), (m+8,k8-15)
    const int klA = (tr_q >> 1) * 8 + tr_r;
    const int mbA = (tr_q & 1) * 16;
    // A normal (64B rows)
    const int aRow = (lane & 7) + ((lane >> 3) & 1) * 8;
    const int aKB  = (lane >> 4) * 16;

    auto compute_chunk = [&](int stage) {
        const uint32_t sb  = smb + stage * STAGEB;
        const uint32_t tAh = sb;
        const uint32_t tAl = sb + MATB;
        const uint32_t tBh = sb + 2 * MATB;
        const uint32_t tBl = sb + 3 * MATB;
#pragma unroll
        for (int ks = 0; ks < 2; ks++) {
            uint32_t bh[4][2], bl[4][2];
#pragma unroll
            for (int nfb = 0; nfb < 4; nfb += 2) {
                const int kr = ks * 16 + klB;
                const int nb = (wn * 32 + nfb * 8) * 2 + nbB;
                uint32_t r[4];
                ldm_x4t(r, tBh + SWZ256(kr, nb));
                bh[nfb][0] = r[0]; bh[nfb][1] = r[1];
                bh[nfb + 1][0] = r[2]; bh[nfb + 1][1] = r[3];
                ldm_x4t(r, tBl + SWZ256(kr, nb));
                bl[nfb][0] = r[0]; bl[nfb][1] = r[1];
                bl[nfb + 1][0] = r[2]; bl[nfb + 1][1] = r[3];
            }
#pragma unroll
            for (int mf = 0; mf < 4; mf++) {
                uint32_t ah[4], al[4];
                if (trA) {
                    const int kr = ks * 16 + klA;
                    const int mb = (wm * 64 + mf * 16) * 2 + mbA;
                    ldm_x4t(ah, tAh + SWZ256(kr, mb));
                    ldm_x4t(al, tAl + SWZ256(kr, mb));
                } else {
                    const int rr = wm * 64 + mf * 16 + aRow;
                    const int kb = ks * 32 + aKB;
                    ldm_x4(ah, tAh + SWZ64(rr, kb));
                    ldm_x4(al, tAl + SWZ64(rr, kb));
                }
#pragma unroll
                for (int nf = 0; nf < 4; nf++) {
                    mma16816(acc[mf][nf], ah, bh[nf]);
                    mma16816(acc[mf][nf], ah, bl[nf]);
                    mma16816(acc[mf][nf], al, bh[nf]);
                }
            }
        }
    };

    // 3-stage pipeline with 2-chunk lookahead
    load_chunk(0, 0);
    CP_COMMIT();
    load_chunk(1, 1);
    CP_COMMIT();
    for (int c = 0; c < nch; c++) {
        if (c + 1 < nch) CP_WAIT1(); else CP_WAIT0();
        __syncthreads();
        if (c + 2 < nch) {
            load_chunk(c + 2, (c + 2) % 3);
            CP_COMMIT();
        }
        compute_chunk(c % 3);
    }

    // ---- epilogues ----
    if (OUTF || OUTHL) {
#pragma unroll
        for (int mf = 0; mf < 4; mf++) {
#pragma unroll
            for (int nf = 0; nf < 4; nf++) {
                const int mr0 = m0 + wm * 64 + mf * 16 + g;
                const int mr1 = mr0 + 8;
                const int n0  = wn * 32 + nf * 8 + 2 * t;
                const float* cc = acc[mf][nf];
                if (OUTF) {
                    if (mr0 < A.Mvalid)
                        *(float2*)(A.Cf + z * A.sC + (long)mr0 * 128 + n0) =
                            make_float2(cc[0], cc[1]);
                    if (mr1 < A.Mvalid)
                        *(float2*)(A.Cf + z * A.sC + (long)mr1 * 128 + n0) =
                            make_float2(cc[2], cc[3]);
                }
                if (OUTHL) {
                    bf16 h0, l0, h1, l1, h2, l2, h3, l3;
                    split2(cc[0], h0, l0); split2(cc[1], h1, l1);
                    split2(cc[2], h2, l2); split2(cc[3], h3, l3);
                    if (mr0 < A.Mvalid) {
                        *(uint32_t*)(A.Chi + z * A.sHL + (long)mr0 * 128 + n0) =
                            pack_bf2(h0, h1);
                        *(uint32_t*)(A.Clo + z * A.sHL + (long)mr0 * 128 + n0) =
                            pack_bf2(l0, l1);
                    }
                    if (mr1 < A.Mvalid) {
                        *(uint32_t*)(A.Chi + z * A.sHL + (long)mr1 * 128 + n0) =
                            pack_bf2(h2, h3);
                        *(uint32_t*)(A.Clo + z * A.sHL + (long)mr1 * 128 + n0) =
                            pack_bf2(l2, l3);
                    }
                }
            }
        }
    }

    if (OUTS) {
        __syncthreads();                    // smem stages dead -> reuse
        float* part = (float*)sm;           // [4][128]
#pragma unroll
        for (int mf = 0; mf < 4; mf++) {
#pragma unroll
            for (int half = 0; half < 2; half++) {
                const int ml = wm * 64 + mf * 16 + half * 8 + g;
                const int mr = m0 + ml;
                float val = 0.f;
                if (mr < A.Mvalid) {
                    const float* up = A.Uf + z * A.sU + (long)mr * 128;
#pragma unroll
                    for (int nf = 0; nf < 4; nf++) {
                        const int n = wn * 32 + nf * 8 + 2 * t;
                        float2 u = *(const float2*)(up + n);
                        val += tanhf(u.x + acc[mf][nf][half * 2 + 0]) * s_wh[n];
                        val += tanhf(u.y + acc[mf][nf][half * 2 + 1]) * s_wh[n + 1];
                    }
                }
                val += __shfl_xor_sync(0xffffffffu, val, 1);
                val += __shfl_xor_sync(0xffffffffu, val, 2);
                if (t == 0) part[wn * 128 + ml] = val;
            }
        }
        __syncthreads();
        if (tid < 128) {
            const int mr = m0 + tid;
            if (mr < A.Mvalid) {
                float s = part[tid] + part[128 + tid] + part[256 + tid] + part[384 + tid];
                A.Sout[z * A.sS + mr] = s;
            }
        }
    }
}

// ===========================================================================
// Tail kernels
// ===========================================================================
__global__ void softmax_kernel(float* __restrict__ s, int L)
{
    float* row = s + (long)blockIdx.x * L;
    __shared__ float red[32];
    __shared__ float bval;
    const int tid  = threadIdx.x;
    const int lane = tid & 31;
    const int wid  = tid >> 5;
    const int nw   = blockDim.x >> 5;

    float m = -1e30f;
    for (int i = tid; i < L; i += blockDim.x) m = fmaxf(m, row[i]);
#pragma unroll
    for (int o = 16; o > 0; o >>= 1) m = fmaxf(m, __shfl_xor_sync(0xffffffffu, m, o));
    if (lane == 0) red[wid] = m;
    __syncthreads();
    if (tid == 0) {
        float mm = red[0];
        for (int w = 1; w < nw; w++) mm = fmaxf(mm, red[w]);
        bval = mm;
    }
    __syncthreads();
    m = bval;
    __syncthreads();

    float sum = 0.f;
    for (int i = tid; i < L; i += blockDim.x) {
        float e = expf(row[i] - m);
        row[i] = e;
        sum += e;
    }
#pragma unroll
    for (int o = 16; o > 0; o >>= 1) sum += __shfl_xor_sync(0xffffffffu, sum, o);
    if (lane == 0) red[wid] = sum;
    __syncthreads();
    if (tid == 0) {
        float ss = 0.f;
        for (int w = 0; w < nw; w++) ss += red[w];
        bval = ss;
    }
    __syncthreads();
    float inv = 1.f / bval;
    for (int i = tid; i < L; i += blockDim.x) row[i] *= inv;
}

__global__ void __launch_bounds__(768) context_kernel(
    const float* __restrict__ T, const float* __restrict__ I,
    const float* __restrict__ aq, const float* __restrict__ av,
    float* __restrict__ ctx)
{
    __shared__ float sq[cfg::LT];
    __shared__ float sv[cfg::LV];
    const int b = blockIdx.x;
    const int d = threadIdx.x;
    for (int i = d; i < cfg::LT; i += 768) sq[i] = aq[(long)b * cfg::LT + i];
    if (d < cfg::LV) sv[d] = av[(long)b * cfg::LV + d];
    __syncthreads();

    const float* Ib = I + (long)b * cfg::LV * cfg::E + d;
    const float* Tb = T + (long)b * cfg::LT * cfg::E + d;
    float acc = 0.f;
#pragma unroll 4
    for (int y = 0; y < cfg::LV; y++) acc += sv[y] * Ib[(long)y * cfg::E];
#pragma unroll 4
    for (int x = 0; x < cfg::LT; x++) acc += sq[x] * Tb[(long)x * cfg::E];
    ctx[(long)b * cfg::E + d] = acc;
}

__global__ void __launch_bounds__(768) out_kernel(
    const float* __restrict__ ctx, const float* __restrict__ ws,
    float* __restrict__ out)
{
    __shared__ float sc[cfg::E];
    const int b = blockIdx.x;
    const int e = threadIdx.x;
    sc[e] = ctx[(long)b * cfg::E + e];
    __syncthreads();
    float acc = 0.f;
#pragma unroll 8
    for (int d = 0; d < cfg::E; d++)
        acc += sc[d] * ws[(long)d * cfg::E + e];
    out[(long)b * cfg::E + e] = tanhf(acc);
}

// ===========================================================================
// launch
// ===========================================================================
extern "C" void kernel_launch(void* const* d_in, const int* in_sizes, int n_in,
                              void* d_out, int out_size)
{
    using namespace cfg;
    const float* T   = (const float*)d_in[0];
    const float* I   = (const float*)d_in[1];
    const float* wb  = (const float*)d_in[3];
    const float* wv  = (const float*)d_in[4];
    const float* wq  = (const float*)d_in[5];
    const float* whv = (const float*)d_in[6];
    const float* whq = (const float*)d_in[7];
    const float* ws  = (const float*)d_in[8];
    float* out = (float*)d_out;

    bf16 *Thi, *Tlo, *Ihi, *Ilo, *wbhi, *wblo, *wqhi, *wqlo, *wvhi, *wvlo;
    bf16 *wqqhi, *wqqlo, *wvvhi, *wvvlo;
    bf16 *A1hi, *A1lo, *M1hi, *M1lo, *A2hi, *A2lo, *Hhi, *Hlo;
    float *wqq, *wvv, *sv, *sq, *ctx;

    cudaGetSymbolAddress((void**)&Thi, g_Thi);   cudaGetSymbolAddress((void**)&Tlo, g_Tlo);
    cudaGetSymbolAddress((void**)&Ihi, g_Ihi);   cudaGetSymbolAddress((void**)&Ilo, g_Ilo);
    cudaGetSymbolAddress((void**)&wbhi, g_wbhi); cudaGetSymbolAddress((void**)&wblo, g_wblo);
    cudaGetSymbolAddress((void**)&wqhi, g_wqhi); cudaGetSymbolAddress((void**)&wqlo, g_wqlo);
    cudaGetSymbolAddress((void**)&wvhi, g_wvhi); cudaGetSymbolAddress((void**)&wvlo, g_wvlo);
    cudaGetSymbolAddress((void**)&wqqhi, g_wqqhi); cudaGetSymbolAddress((void**)&wqqlo, g_wqqlo);
    cudaGetSymbolAddress((void**)&wvvhi, g_wvvhi); cudaGetSymbolAddress((void**)&wvvlo, g_wvvlo);
    cudaGetSymbolAddress((void**)&A1hi, g_A1hi); cudaGetSymbolAddress((void**)&A1lo, g_A1lo);
    cudaGetSymbolAddress((void**)&M1hi, g_M1hi); cudaGetSymbolAddress((void**)&M1lo, g_M1lo);
    cudaGetSymbolAddress((void**)&A2hi, g_A2hi); cudaGetSymbolAddress((void**)&A2lo, g_A2lo);
    cudaGetSymbolAddress((void**)&Hhi, g_Hhi);   cudaGetSymbolAddress((void**)&Hlo, g_Hlo);
    cudaGetSymbolAddress((void**)&wqq, g_wqq);   cudaGetSymbolAddress((void**)&wvv, g_wvv);
    cudaGetSymbolAddress((void**)&sv, g_sv);     cudaGetSymbolAddress((void**)&sq, g_sq);
    cudaGetSymbolAddress((void**)&ctx, g_ctx);

    cudaFuncSetAttribute(mma_gemm<true, true, false>,
        cudaFuncAttributeMaxDynamicSharedMemorySize, SMEM_MMA_BYTES);
    cudaFuncSetAttribute(mma_gemm<false, true, false>,
        cudaFuncAttributeMaxDynamicSharedMemorySize, SMEM_MMA_BYTES);
    cudaFuncSetAttribute(mma_gemm<false, false, true>,
        cudaFuncAttributeMaxDynamicSharedMemorySize, SMEM_MMA_BYTES);

    // --- conversions (flat hi/lo only) ---
    {
        long nT = (long)Bn * LT * E / 4, nI = (long)Bn * LV * E / 4;
        long nWb = (long)E * E / 4, nW = (long)E * Kd / 4;
        conv_flat<<<(unsigned)((nT + 255) / 256), 256>>>(T, Thi, Tlo, nT);
        conv_flat<<<(unsigned)((nI + 255) / 256), 256>>>(I, Ihi, Ilo, nI);
        conv_flat<<<(unsigned)((nWb + 255) / 256), 256>>>(wb, wbhi, wblo, nWb);
        conv_flat<<<(unsigned)((nW + 255) / 256), 256>>>(wq, wqhi, wqlo, nW);
        conv_flat<<<(unsigned)((nW + 255) / 256), 256>>>(wv, wvhi, wvlo, nW);
    }

    GArgs Z{};  // zero template

    // L1: G1 wqq = T@wq (flat M=65536) | G2 wvv = I@wv (flat M=36864)
    {
        GArgs a0 = Z, a1 = Z;
        a0.Ahi = Thi; a0.Alo = Tlo; a0.Bhi = wqhi; a0.Blo = wqlo;
        a0.Cf = wqq; a0.Chi = wqqhi; a0.Clo = wqqlo;
        a0.Ktot = E; a0.Mvalid = Bn * LT;
        a1.Ahi = Ihi; a1.Alo = Ilo; a1.Bhi = wvhi; a1.Blo = wvlo;
        a1.Cf = wvv; a1.Chi = wvvhi; a1.Clo = wvvlo;
        a1.Ktot = E; a1.Mvalid = Bn * LV;
        mma_gemm<true, true, false><<<dim3(512 + 288, 1, 1), 256, SMEM_MMA_BYTES>>>(
            a0, a1, 512);
    }
    // L2: G3 A1 = T^T@wqq (transA, K=1024) | G6 A2 = I^T@wvv (transA, K=576)
    {
        GArgs a0 = Z, a1 = Z;
        a0.Ahi = Thi; a0.Alo = Tlo; a0.sA = (long)LT * E; a0.transA = 1;
        a0.Bhi = wqqhi; a0.Blo = wqqlo; a0.sB = (long)LT * Kd;
        a0.Chi = A1hi; a0.Clo = A1lo; a0.sHL = (long)E * Kd;
        a0.Ktot = LT; a0.Mvalid = E;
        a1.Ahi = Ihi; a1.Alo = Ilo; a1.sA = (long)LV * E; a1.transA = 1;
        a1.Bhi = wvvhi; a1.Blo = wvvlo; a1.sB = (long)LV * Kd;
        a1.Chi = A2hi; a1.Clo = A2lo; a1.sHL = (long)E * Kd;
        a1.Ktot = LV; a1.Mvalid = E;
        mma_gemm<false, true, false><<<dim3(12, 1, Bn), 256, SMEM_MMA_BYTES>>>(
            a0, a1, 6);
    }
    // L3: G4 M1 = wb^T@A1 (transA) | G7 H = wb@A2 (normal A)
    {
        GArgs a0 = Z, a1 = Z;
        a0.Ahi = wbhi; a0.Alo = wblo; a0.transA = 1;
        a0.Bhi = A1hi; a0.Blo = A1lo; a0.sB = (long)E * Kd;
        a0.Chi = M1hi; a0.Clo = M1lo; a0.sHL = (long)E * Kd;
        a0.Ktot = E; a0.Mvalid = E;
        a1.Ahi = wbhi; a1.Alo = wblo; a1.transA = 0;
        a1.Bhi = A2hi; a1.Blo = A2lo; a1.sB = (long)E * Kd;
        a1.Chi = Hhi; a1.Clo = Hlo; a1.sHL = (long)E * Kd;
        a1.Ktot = E; a1.Mvalid = E;
        mma_gemm<false, true, false><<<dim3(12, 1, Bn), 256, SMEM_MMA_BYTES>>>(
            a0, a1, 6);
    }
    // L4: G5 sv = score(I@M1 + wvv) | G8 sq = score(T@H + wqq)
    {
        GArgs a0 = Z, a1 = Z;
        a0.Ahi = Ihi; a0.Alo = Ilo; a0.sA = (long)LV * E;
        a0.Bhi = M1hi; a0.Blo = M1lo; a0.sB = (long)E * Kd;
        a0.Uf = wvv; a0.sU = (long)LV * Kd; a0.wh = whv;
        a0.Sout = sv; a0.sS = LV;
        a0.Ktot = E; a0.Mvalid = LV;
        a1.Ahi = Thi; a1.Alo = Tlo; a1.sA = (long)LT * E;
        a1.Bhi = Hhi; a1.Blo = Hlo; a1.sB = (long)E * Kd;
        a1.Uf = wqq; a1.sU = (long)LT * Kd; a1.wh = whq;
        a1.Sout = sq; a1.sS = LT;
        a1.Ktot = E; a1.Mvalid = LT;
        mma_gemm<false, false, true><<<dim3(5 + 8, 1, Bn), 256, SMEM_MMA_BYTES>>>(
            a0, a1, 5);
    }

    // --- softmax / context / output ---
    softmax_kernel<<<Bn, 256>>>(sv, LV);
    softmax_kernel<<<Bn, 256>>>(sq, LT);
    context_kernel<<<Bn, 768>>>(T, I, sq, sv, ctx);
    out_kernel<<<Bn, 768>>>(ctx, ws, out);
}